// round 2
// baseline (speedup 1.0000x reference)
#include <cuda_runtime.h>
#include <cuda_bf16.h>

// Problem constants (fixed shapes per reference)
#define Nn 50000
#define Ee 800000
#define Dd 256
#define Hh 8
#define Cc 32
#define EDd 16
#define Ll 6
#define D4 (4*Dd)

// ---------------- device scratch (no allocations allowed) ----------------
__device__ float    g_m    [Nn*Dd];
__device__ float    g_xp   [Nn*Dd];
__device__ float    g_gat  [Nn*Dd];
__device__ float    g_m1   [Nn*Dd];
__device__ float    g_hbuf [Nn*D4];
__device__ float    g_h2   [Nn*Dd];
__device__ float    g_alpha[(Ee+Nn)*Hh];
__device__ float    g_aedge[(Ee+Nn)*Hh];
__device__ float    g_asrc [Nn*Hh];
__device__ float    g_adst [Nn*Hh];
__device__ unsigned g_amax [Nn*Hh];
__device__ float    g_denom[Nn*Hh];
__device__ float    g_deg  [Nn];
__device__ float    g_easum[Nn*EDd];
__device__ float    g_eamean[Nn*EDd];
__device__ float    g_v    [EDd*Hh];
__device__ int      g_src32[Ee];
__device__ int      g_dst32[Ee];

// order-preserving float<->uint for atomicMax
__device__ __forceinline__ unsigned f2o(float f) {
    unsigned u = __float_as_uint(f);
    return (u & 0x80000000u) ? ~u : (u | 0x80000000u);
}
__device__ __forceinline__ float o2f(unsigned u) {
    return __uint_as_float((u & 0x80000000u) ? (u ^ 0x80000000u) : ~u);
}
__device__ __forceinline__ float lrelu(float x) { return x > 0.f ? x : 0.2f * x; }
__device__ __forceinline__ int clampN(int v) { return v < 0 ? 0 : (v >= Nn ? Nn - 1 : v); }

// ---------------- index conversion with on-device dtype detection ----------------
// The reference uses int64 edge_index, but the harness may deliver int32.
// Detect: read first 8 elements as int64 — true int64 indices are all in [0, N);
// if the buffer is really int32, the reinterpreted values contain random high
// words and at least one is >= N. Every thread computes the same flag.
__global__ void convert_idx_kernel(const void* eiraw, int* src32, int* dst32) {
    const long long* ei64 = (const long long*)eiraw;
    bool is64 = true;
    #pragma unroll
    for (int k = 0; k < 8; ++k) {
        unsigned long long v = (unsigned long long)ei64[k];
        if (v >= (unsigned long long)Nn) is64 = false;
    }
    int e = blockIdx.x * blockDim.x + threadIdx.x;
    if (e >= Ee) return;
    int s, d;
    if (is64) {
        s = (int)ei64[e];
        d = (int)ei64[e + Ee];
    } else {
        const int* ei32 = (const int*)eiraw;
        s = ei32[e];
        d = ei32[e + Ee];
    }
    src32[e] = clampN(s);
    dst32[e] = clampN(d);
}

// ---------------- small utility kernels ----------------
__global__ void copy_kernel(float* __restrict__ dst, const float* __restrict__ src, int n) {
    int i = blockIdx.x * blockDim.x + threadIdx.x;
    if (i < n) dst[i] = src[i];
}
__global__ void zero_kernel(float* __restrict__ p, int n) {
    int i = blockIdx.x * blockDim.x + threadIdx.x;
    if (i < n) p[i] = 0.f;
}

// deg + edge_attr segment-sum over destination
__global__ void deg_easum_kernel(const int* __restrict__ dst,
                                 const float* __restrict__ ea,
                                 float* __restrict__ deg, float* __restrict__ easum) {
    int idx = blockIdx.x * blockDim.x + threadIdx.x;
    if (idx >= Ee * EDd) return;
    int e = idx >> 4, j = idx & 15;
    int d = dst[e];
    atomicAdd(&easum[d * EDd + j], ea[idx]);
    if (j == 0) atomicAdd(&deg[d], 1.0f);
}
__global__ void eamean_kernel(const float* __restrict__ easum, const float* __restrict__ deg,
                              float* __restrict__ eamean) {
    int idx = blockIdx.x * blockDim.x + threadIdx.x;
    if (idx >= Nn * EDd) return;
    int n = idx >> 4;
    eamean[idx] = easum[idx] / fmaxf(deg[n], 1.0f);
}
// v[d,h] = sum_c W_edge[d, h*32+c] * att_edge[h,c]
__global__ void v_kernel(const float* __restrict__ W_edge, const float* __restrict__ att_edge,
                         float* __restrict__ v) {
    int t = threadIdx.x;
    if (t >= EDd * Hh) return;
    int d = t >> 3, h = t & 7;
    float s = 0.f;
    #pragma unroll
    for (int c = 0; c < Cc; ++c) s += W_edge[d * Dd + h * Cc + c] * att_edge[h * Cc + c];
    v[d * Hh + h] = s;
}
// a_edge[e,h] for real edges and self loops (layer-invariant)
__global__ void aedge_kernel(const float* __restrict__ ea, const float* __restrict__ eamean,
                             const float* __restrict__ v, float* __restrict__ aedge) {
    int e = blockIdx.x * blockDim.x + threadIdx.x;
    if (e >= Ee + Nn) return;
    const float* p = (e < Ee) ? (ea + (size_t)e * EDd) : (eamean + (size_t)(e - Ee) * EDd);
    float r[EDd];
    #pragma unroll
    for (int j = 0; j < EDd; ++j) r[j] = p[j];
    #pragma unroll
    for (int h = 0; h < Hh; ++h) {
        float s = 0.f;
        #pragma unroll
        for (int j = 0; j < EDd; ++j) s += r[j] * v[j * Hh + h];
        aedge[(size_t)e * Hh + h] = s;
    }
}

// per (node, head): a_src/a_dst, self-loop alpha, init amax/denom
__global__ void attscore_kernel(const float* __restrict__ xp,
                                const float* __restrict__ att_src, const float* __restrict__ att_dst,
                                const float* __restrict__ aedge,
                                float* __restrict__ asrc, float* __restrict__ adst,
                                unsigned* __restrict__ amax, float* __restrict__ denom,
                                float* __restrict__ alpha) {
    int idx = blockIdx.x * blockDim.x + threadIdx.x;
    if (idx >= Nn * Hh) return;
    int n = idx >> 3, h = idx & 7;
    const float* xr = xp + (size_t)n * Dd + h * Cc;
    float s = 0.f, dd = 0.f;
    #pragma unroll
    for (int c = 0; c < Cc; ++c) {
        float vv = xr[c];
        s  += vv * att_src[h * Cc + c];
        dd += vv * att_dst[h * Cc + c];
    }
    asrc[idx] = s;
    adst[idx] = dd;
    float al = lrelu(s + dd + aedge[(size_t)(Ee + n) * Hh + h]);
    alpha[(size_t)(Ee + n) * Hh + h] = al;
    amax[idx]  = f2o(al);
    denom[idx] = 0.f;
}

// per (edge, head): alpha + running segment max
__global__ void edge_alpha_kernel(const int* __restrict__ src, const int* __restrict__ dst,
                                  const float* __restrict__ asrc, const float* __restrict__ adst,
                                  const float* __restrict__ aedge,
                                  float* __restrict__ alpha, unsigned* __restrict__ amax) {
    int idx = blockIdx.x * blockDim.x + threadIdx.x;
    if (idx >= Ee * Hh) return;
    int e = idx >> 3, h = idx & 7;
    int s = src[e], d = dst[e];
    float al = lrelu(asrc[s * Hh + h] + adst[d * Hh + h] + aedge[idx]);
    alpha[idx] = al;
    atomicMax(&amax[d * Hh + h], f2o(al));
}

// per (edge-incl-selfloop, head): denom accumulation
__global__ void denom_kernel(const int* __restrict__ dst,
                             const float* __restrict__ alpha, const unsigned* __restrict__ amax,
                             float* __restrict__ denom) {
    int idx = blockIdx.x * blockDim.x + threadIdx.x;
    if (idx >= (Ee + Nn) * Hh) return;
    int e = idx >> 3, h = idx & 7;
    int d = (e < Ee) ? dst[e] : (e - Ee);
    float ex = expf(alpha[idx] - o2f(amax[d * Hh + h]));
    atomicAdd(&denom[d * Hh + h], ex);
}

// warp per (edge, head): weighted scatter of 32 channels
__global__ void agg_kernel(const int* __restrict__ src, const int* __restrict__ dst,
                           const float* __restrict__ alpha, const unsigned* __restrict__ amax,
                           const float* __restrict__ denom, const float* __restrict__ xp,
                           float* __restrict__ out) {
    long long tidg = (long long)blockIdx.x * blockDim.x + threadIdx.x;
    long long g = tidg >> 5;
    int lane = threadIdx.x & 31;
    if (g >= (long long)(Ee + Nn) * Hh) return;
    int e = (int)(g >> 3), h = (int)(g & 7);
    int s, d;
    if (e < Ee) { s = src[e]; d = dst[e]; }
    else        { s = d = e - Ee; }
    int dh = d * Hh + h;
    float w = expf(alpha[g] - o2f(amax[dh])) / denom[dh];
    float val = xp[(size_t)s * Dd + h * Cc + lane] * w;
    atomicAdd(&out[(size_t)d * Dd + h * Cc + lane], val);
}

// LayerNorm over D=256 of (a + b [+ bias]); one block per row, 256 threads
__global__ void ln_kernel(const float* __restrict__ a, const float* __restrict__ b,
                          const float* __restrict__ bias,
                          const float* __restrict__ gamma, const float* __restrict__ beta,
                          float* __restrict__ out) {
    int n = blockIdx.x;
    int t = threadIdx.x;
    size_t off = (size_t)n * Dd + t;
    float r = a[off] + b[off];
    if (bias) r += bias[t];
    __shared__ float sh[40];
    float s = r;
    #pragma unroll
    for (int o = 16; o; o >>= 1) s += __shfl_xor_sync(0xffffffffu, s, o);
    if ((t & 31) == 0) sh[t >> 5] = s;
    __syncthreads();
    if (t < 8) {
        float v = sh[t];
        #pragma unroll
        for (int o = 4; o; o >>= 1) v += __shfl_xor_sync(0xffu, v, o);
        if (t == 0) sh[32] = v;
    }
    __syncthreads();
    float mean = sh[32] * (1.0f / Dd);
    float dv = r - mean;
    float sq = dv * dv;
    #pragma unroll
    for (int o = 16; o; o >>= 1) sq += __shfl_xor_sync(0xffffffffu, sq, o);
    if ((t & 31) == 0) sh[t >> 5] = sq;
    __syncthreads();
    if (t < 8) {
        float v = sh[t];
        #pragma unroll
        for (int o = 4; o; o >>= 1) v += __shfl_xor_sync(0xffu, v, o);
        if (t == 0) sh[33] = v;
    }
    __syncthreads();
    float var = sh[33] * (1.0f / Dd);
    out[off] = dv * rsqrtf(var + 1e-5f) * gamma[t] + beta[t];
}

// ---------------- SGEMM: C[M,N] = A[M,K] @ B[K,N] (+bias)(+relu) ----------------
template<bool BIAS, bool RELU>
__global__ void __launch_bounds__(256) sgemm128(int M, int N, int K,
                                                const float* __restrict__ A,
                                                const float* __restrict__ B,
                                                const float* __restrict__ bias,
                                                float* __restrict__ C) {
    const int BM = 128, BN = 128, BK = 8, TM = 8, TN = 8;
    __shared__ float As[BK * BM];
    __shared__ float Bs[BK * BN];
    int cRow = blockIdx.y, cCol = blockIdx.x;
    int tid = threadIdx.x;
    int threadCol = tid % (BN / TN);
    int threadRow = tid / (BN / TN);
    int innerRowA = tid >> 1;
    int innerColA = (tid & 1) * 4;
    int innerRowB = tid >> 5;
    int innerColB = (tid & 31) * 4;
    const float* Ab = A + (size_t)cRow * BM * K;
    const float* Bb = B + (size_t)cCol * BN;
    float* Cb = C + (size_t)cRow * BM * N + (size_t)cCol * BN;
    int aRowGlobal = cRow * BM + innerRowA;

    float acc[TM][TN] = {};
    float regM[TM], regN[TN];

    for (int k0 = 0; k0 < K; k0 += BK) {
        float4 av;
        if (aRowGlobal < M)
            av = *reinterpret_cast<const float4*>(Ab + (size_t)innerRowA * K + k0 + innerColA);
        else
            av = make_float4(0.f, 0.f, 0.f, 0.f);
        As[(innerColA + 0) * BM + innerRowA] = av.x;
        As[(innerColA + 1) * BM + innerRowA] = av.y;
        As[(innerColA + 2) * BM + innerRowA] = av.z;
        As[(innerColA + 3) * BM + innerRowA] = av.w;
        float4 bv = *reinterpret_cast<const float4*>(Bb + (size_t)(k0 + innerRowB) * N + innerColB);
        *reinterpret_cast<float4*>(&Bs[innerRowB * BN + innerColB]) = bv;
        __syncthreads();
        #pragma unroll
        for (int k = 0; k < BK; ++k) {
            #pragma unroll
            for (int i = 0; i < TM; ++i) regM[i] = As[k * BM + threadRow * TM + i];
            #pragma unroll
            for (int j = 0; j < TN; ++j) regN[j] = Bs[k * BN + threadCol * TN + j];
            #pragma unroll
            for (int i = 0; i < TM; ++i)
                #pragma unroll
                for (int j = 0; j < TN; ++j)
                    acc[i][j] += regM[i] * regN[j];
        }
        __syncthreads();
    }
    #pragma unroll
    for (int i = 0; i < TM; ++i) {
        int row = cRow * BM + threadRow * TM + i;
        if (row >= M) break;
        #pragma unroll
        for (int j = 0; j < TN; j += 4) {
            float4 v;
            v.x = acc[i][j]; v.y = acc[i][j + 1]; v.z = acc[i][j + 2]; v.w = acc[i][j + 3];
            if (BIAS) {
                int col = cCol * BN + threadCol * TN + j;
                v.x += bias[col]; v.y += bias[col + 1]; v.z += bias[col + 2]; v.w += bias[col + 3];
            }
            if (RELU) {
                v.x = fmaxf(v.x, 0.f); v.y = fmaxf(v.y, 0.f);
                v.z = fmaxf(v.z, 0.f); v.w = fmaxf(v.w, 0.f);
            }
            *reinterpret_cast<float4*>(Cb + (size_t)(threadRow * TM + i) * N + threadCol * TN + j) = v;
        }
    }
}

// ---------------- orchestration ----------------
static inline float* symaddr(const void* sym) {
    void* p = nullptr;
    cudaGetSymbolAddress(&p, sym);
    return (float*)p;
}

extern "C" void kernel_launch(void* const* d_in, const int* in_sizes, int n_in,
                              void* d_out, int out_size) {
    const float*     x        = (const float*)d_in[0];
    const void*      ei       = d_in[1];
    const float*     edge_attr= (const float*)d_in[2];
    const float*     W        = (const float*)d_in[3];
    const float*     att_src  = (const float*)d_in[4];
    const float*     att_dst  = (const float*)d_in[5];
    const float*     att_edge = (const float*)d_in[6];
    const float*     W_edge   = (const float*)d_in[7];
    const float*     bias     = (const float*)d_in[8];
    const float*     ffn_w1   = (const float*)d_in[9];
    const float*     ffn_b1   = (const float*)d_in[10];
    const float*     ffn_w2   = (const float*)d_in[11];
    const float*     ffn_b2   = (const float*)d_in[12];
    const float*     ln1_g    = (const float*)d_in[13];
    const float*     ln1_b    = (const float*)d_in[14];
    const float*     ln2_g    = (const float*)d_in[15];
    const float*     ln2_b    = (const float*)d_in[16];
    float* out = (float*)d_out;

    float*    pm     = symaddr(g_m);
    float*    pxp    = symaddr(g_xp);
    float*    pgat   = symaddr(g_gat);
    float*    pm1    = symaddr(g_m1);
    float*    ph     = symaddr(g_hbuf);
    float*    ph2    = symaddr(g_h2);
    float*    palpha = symaddr(g_alpha);
    float*    paedge = symaddr(g_aedge);
    float*    pasrc  = symaddr(g_asrc);
    float*    padst  = symaddr(g_adst);
    unsigned* pamax  = (unsigned*)symaddr(g_amax);
    float*    pdenom = symaddr(g_denom);
    float*    pdeg   = symaddr(g_deg);
    float*    peasum = symaddr(g_easum);
    float*    peamean= symaddr(g_eamean);
    float*    pv     = symaddr(g_v);
    int*      psrc   = (int*)symaddr(g_src32);
    int*      pdst   = (int*)symaddr(g_dst32);

    const int T = 256;
    auto blk = [](long long n, int t) { return (unsigned)((n + t - 1) / t); };

    // index conversion (dtype-robust)
    convert_idx_kernel<<<blk(Ee, T), T>>>(ei, psrc, pdst);

    // m = x
    copy_kernel<<<blk((long long)Nn * Dd, T), T>>>(pm, x, Nn * Dd);

    // layer-invariant precomputation
    zero_kernel<<<blk(Nn, T), T>>>(pdeg, Nn);
    zero_kernel<<<blk((long long)Nn * EDd, T), T>>>(peasum, Nn * EDd);
    deg_easum_kernel<<<blk((long long)Ee * EDd, T), T>>>(pdst, edge_attr, pdeg, peasum);
    eamean_kernel<<<blk((long long)Nn * EDd, T), T>>>(peasum, pdeg, peamean);
    v_kernel<<<1, 128>>>(W_edge, att_edge, pv);
    aedge_kernel<<<blk((long long)(Ee + Nn), T), T>>>(edge_attr, peamean, pv, paedge);

    dim3 gProj(Dd / 128, (Nn + 127) / 128);
    dim3 gF1(D4 / 128, (Nn + 127) / 128);
    dim3 gF2(Dd / 128, (Nn + 127) / 128);

    for (int i = 0; i < Ll; ++i) {
        sgemm128<false, false><<<gProj, 256>>>(Nn, Dd, Dd, pm, W, nullptr, pxp);
        attscore_kernel<<<blk((long long)Nn * Hh, T), T>>>(pxp, att_src, att_dst, paedge,
                                                           pasrc, padst, pamax, pdenom, palpha);
        zero_kernel<<<blk((long long)Nn * Dd, T), T>>>(pgat, Nn * Dd);
        edge_alpha_kernel<<<blk((long long)Ee * Hh, T), T>>>(psrc, pdst, pasrc, padst, paedge,
                                                             palpha, pamax);
        denom_kernel<<<blk((long long)(Ee + Nn) * Hh, T), T>>>(pdst, palpha, pamax, pdenom);
        agg_kernel<<<blk((long long)(Ee + Nn) * Hh * 32, T), T>>>(psrc, pdst, palpha, pamax, pdenom,
                                                                  pxp, pgat);
        ln_kernel<<<Nn, Dd>>>(pgat, pm, bias, ln1_g + i * Dd, ln1_b + i * Dd, pm1);
        sgemm128<true, true><<<gF1, 256>>>(Nn, D4, Dd, pm1,
                                           ffn_w1 + (size_t)i * Dd * D4, ffn_b1 + (size_t)i * D4, ph);
        sgemm128<true, false><<<gF2, 256>>>(Nn, Dd, D4, ph,
                                            ffn_w2 + (size_t)i * D4 * Dd, ffn_b2 + (size_t)i * Dd, ph2);
        ln_kernel<<<Nn, Dd>>>(ph2, pm1, nullptr, ln2_g + i * Dd, ln2_b + i * Dd, pm);
    }

    copy_kernel<<<blk((long long)Nn * Dd, T), T>>>(out, pm, Nn * Dd);
}

// round 3
// speedup vs baseline: 1.4168x; 1.4168x over previous
#include <cuda_runtime.h>
#include <cuda_bf16.h>

// Problem constants (fixed shapes per reference)
#define Nn 50000
#define Ee 800000
#define Dd 256
#define Hh 8
#define Cc 32
#define EDd 16
#define Ll 6
#define D4 (4*Dd)

// ---------------- device scratch ----------------
__device__ float    g_m    [Nn*Dd];
__device__ float    g_xp   [Nn*Dd];
__device__ float    g_m1   [Nn*Dd];
__device__ float    g_hbuf [Nn*D4];
__device__ float    g_h2   [Nn*Dd];
__device__ float    g_w    [Ee*Hh];        // normalized attention weights (CSR order)
__device__ float    g_wself[Nn*Hh];        // self-loop weights
__device__ float    g_aedge[(Ee+Nn)*Hh];   // edge attention term, CSR order; self at Ee+n
__device__ float    g_asrc [Nn*Hh];
__device__ float    g_adst [Nn*Hh];
__device__ float    g_easum[Nn*EDd];
__device__ float    g_eamean[Nn*EDd];
__device__ float    g_v    [EDd*Hh];
__device__ int      g_src32[Ee];
__device__ int      g_dst32[Ee];
__device__ int      g_degi [Nn];
__device__ int      g_offs [Nn+1];
__device__ int      g_cursor[Nn];
__device__ int      g_csrc [Ee];           // src node per CSR position
__device__ int      g_posof[Ee];           // edge id -> CSR position

__device__ __forceinline__ float lrelu(float x) { return x > 0.f ? x : 0.2f * x; }
__device__ __forceinline__ int clampN(int v) { return v < 0 ? 0 : (v >= Nn ? Nn - 1 : v); }
__device__ __forceinline__ float wred_max(float v) {
    #pragma unroll
    for (int o = 16; o; o >>= 1) v = fmaxf(v, __shfl_xor_sync(0xffffffffu, v, o));
    return v;
}
__device__ __forceinline__ float wred_sum(float v) {
    #pragma unroll
    for (int o = 16; o; o >>= 1) v += __shfl_xor_sync(0xffffffffu, v, o);
    return v;
}

// ---------------- index conversion with on-device dtype detection ----------------
__global__ void convert_idx_kernel(const void* eiraw, int* src32, int* dst32, int* degi) {
    const long long* ei64 = (const long long*)eiraw;
    bool is64 = true;
    #pragma unroll
    for (int k = 0; k < 8; ++k) {
        unsigned long long v = (unsigned long long)ei64[k];
        if (v >= (unsigned long long)Nn) is64 = false;
    }
    int e = blockIdx.x * blockDim.x + threadIdx.x;
    if (e >= Ee) return;
    int s, d;
    if (is64) { s = (int)ei64[e]; d = (int)ei64[e + Ee]; }
    else      { const int* ei32 = (const int*)eiraw; s = ei32[e]; d = ei32[e + Ee]; }
    s = clampN(s); d = clampN(d);
    src32[e] = s;
    dst32[e] = d;
    atomicAdd(&degi[d], 1);
}

// ---------------- small utility kernels ----------------
__global__ void copy_kernel(float* __restrict__ dst, const float* __restrict__ src, int n) {
    int i = blockIdx.x * blockDim.x + threadIdx.x;
    if (i < n) dst[i] = src[i];
}
__global__ void zerof_kernel(float* __restrict__ p, int n) {
    int i = blockIdx.x * blockDim.x + threadIdx.x;
    if (i < n) p[i] = 0.f;
}
__global__ void zeroi_kernel(int* __restrict__ p, int n) {
    int i = blockIdx.x * blockDim.x + threadIdx.x;
    if (i < n) p[i] = 0;
}

// single-block exclusive scan of degrees -> offsets + cursor copy
__global__ void scan_kernel(const int* __restrict__ degi, int* __restrict__ offs,
                            int* __restrict__ cursor) {
    __shared__ int part[256];
    int t = threadIdx.x;
    const int CH = (Nn + 255) / 256;
    int s = 0;
    for (int i = 0; i < CH; ++i) {
        int idx = t * CH + i;
        if (idx < Nn) s += degi[idx];
    }
    part[t] = s;
    __syncthreads();
    if (t == 0) {
        int acc = 0;
        for (int i = 0; i < 256; ++i) { int v = part[i]; part[i] = acc; acc += v; }
    }
    __syncthreads();
    int run = part[t];
    for (int i = 0; i < CH; ++i) {
        int idx = t * CH + i;
        if (idx < Nn) {
            offs[idx] = run;
            cursor[idx] = run;
            run += degi[idx];
        }
    }
    if (t == 0) offs[Nn] = Ee;
}

// scatter edges into CSR order
__global__ void scatter_kernel(const int* __restrict__ src, const int* __restrict__ dst,
                               int* __restrict__ cursor, int* __restrict__ csrc,
                               int* __restrict__ posof) {
    int e = blockIdx.x * blockDim.x + threadIdx.x;
    if (e >= Ee) return;
    int d = dst[e];
    int p = atomicAdd(&cursor[d], 1);
    csrc[p] = src[e];
    posof[e] = p;
}

// edge_attr segment-sum over destination (for self-loop fill)
__global__ void easum_kernel(const int* __restrict__ dst, const float* __restrict__ ea,
                             float* __restrict__ easum) {
    int idx = blockIdx.x * blockDim.x + threadIdx.x;
    if (idx >= Ee * EDd) return;
    int e = idx >> 4, j = idx & 15;
    atomicAdd(&easum[dst[e] * EDd + j], ea[idx]);
}
__global__ void eamean_kernel(const float* __restrict__ easum, const int* __restrict__ degi,
                              float* __restrict__ eamean) {
    int idx = blockIdx.x * blockDim.x + threadIdx.x;
    if (idx >= Nn * EDd) return;
    int n = idx >> 4;
    eamean[idx] = easum[idx] / fmaxf((float)degi[n], 1.0f);
}
// v[d,h] = sum_c W_edge[d, h*32+c] * att_edge[h,c]
__global__ void v_kernel(const float* __restrict__ W_edge, const float* __restrict__ att_edge,
                         float* __restrict__ v) {
    int t = threadIdx.x;
    if (t >= EDd * Hh) return;
    int d = t >> 3, h = t & 7;
    float s = 0.f;
    #pragma unroll
    for (int c = 0; c < Cc; ++c) s += W_edge[d * Dd + h * Cc + c] * att_edge[h * Cc + c];
    v[d * Hh + h] = s;
}
// a_edge in CSR order (real edges via posof; self loops at rows Ee+n)
__global__ void aedge_kernel(const float* __restrict__ ea, const float* __restrict__ eamean,
                             const float* __restrict__ v, const int* __restrict__ posof,
                             float* __restrict__ aedge) {
    int e = blockIdx.x * blockDim.x + threadIdx.x;
    if (e >= Ee + Nn) return;
    const float* p = (e < Ee) ? (ea + (size_t)e * EDd) : (eamean + (size_t)(e - Ee) * EDd);
    float r[EDd];
    #pragma unroll
    for (int j = 0; j < EDd; ++j) r[j] = p[j];
    size_t row = (e < Ee) ? (size_t)posof[e] : (size_t)e;
    #pragma unroll
    for (int h = 0; h < Hh; ++h) {
        float s = 0.f;
        #pragma unroll
        for (int j = 0; j < EDd; ++j) s += r[j] * v[j * Hh + h];
        aedge[row * Hh + h] = s;
    }
}

// warp per (node, head): a_src and a_dst dot products, coalesced
__global__ void asrc_adst_kernel(const float* __restrict__ xp,
                                 const float* __restrict__ att_src,
                                 const float* __restrict__ att_dst,
                                 float* __restrict__ asrc, float* __restrict__ adst) {
    int gw = (blockIdx.x * blockDim.x + threadIdx.x) >> 5;
    int lane = threadIdx.x & 31;
    if (gw >= Nn * Hh) return;
    int n = gw >> 3, h = gw & 7;
    float v = xp[(size_t)n * Dd + h * Cc + lane];
    float s = wred_sum(v * att_src[h * Cc + lane]);
    float d = wred_sum(v * att_dst[h * Cc + lane]);
    if (lane == 0) { asrc[gw] = s; adst[gw] = d; }
}

// warp per (node, head): softmax over incoming edges (CSR), write normalized weights
__global__ void attw_kernel(const int* __restrict__ offs, const int* __restrict__ csrc,
                            const float* __restrict__ asrc, const float* __restrict__ adst,
                            const float* __restrict__ aedge,
                            float* __restrict__ w, float* __restrict__ wself) {
    int gw = (blockIdx.x * blockDim.x + threadIdx.x) >> 5;
    int lane = threadIdx.x & 31;
    if (gw >= Nn * Hh) return;
    int n = gw >> 3, h = gw & 7;
    int off = offs[n];
    int deg = offs[n + 1] - off;
    float adstn = adst[gw];
    float al_self = lrelu(asrc[gw] + adstn + aedge[(size_t)(Ee + n) * Hh + h]);

    if (deg <= 32) {
        float al = -3.4e38f;
        if (lane < deg) {
            int s = csrc[off + lane];
            al = lrelu(asrc[s * Hh + h] + adstn + aedge[(size_t)(off + lane) * Hh + h]);
        }
        float M = fmaxf(al_self, wred_max(al));
        float ex = (lane < deg) ? expf(al - M) : 0.f;
        float exs = expf(al_self - M);
        float denom = exs + wred_sum(ex);
        if (lane < deg) w[(size_t)(off + lane) * Hh + h] = ex / denom;
        if (lane == 0) wself[gw] = exs / denom;
    } else {
        float M = al_self;
        for (int i = lane; i < deg; i += 32) {
            int s = csrc[off + i];
            float al = lrelu(asrc[s * Hh + h] + adstn + aedge[(size_t)(off + i) * Hh + h]);
            w[(size_t)(off + i) * Hh + h] = al;
            M = fmaxf(M, al);
        }
        M = wred_max(M);
        float sum = 0.f;
        for (int i = lane; i < deg; i += 32) {
            float ex = expf(w[(size_t)(off + i) * Hh + h] - M);
            w[(size_t)(off + i) * Hh + h] = ex;
            sum += ex;
        }
        float exs = expf(al_self - M);
        float denom = exs + wred_sum(sum);
        float inv = 1.f / denom;
        for (int i = lane; i < deg; i += 32) w[(size_t)(off + i) * Hh + h] *= inv;
        if (lane == 0) wself[gw] = exs * inv;
    }
}

// block per node: gather-aggregate + bias + residual + LayerNorm1 (fused)
__global__ void __launch_bounds__(256) agg_ln1_kernel(
        const int* __restrict__ offs, const int* __restrict__ csrc,
        const float* __restrict__ w, const float* __restrict__ wself,
        const float* __restrict__ xp, const float* __restrict__ m,
        const float* __restrict__ bias,
        const float* __restrict__ gamma, const float* __restrict__ beta,
        float* __restrict__ out) {
    int n = blockIdx.x;
    int t = threadIdx.x;
    int h = t >> 5, lane = t & 31;
    __shared__ int ssrc[128];
    __shared__ float sh[40];
    __shared__ int soff, sdeg;
    if (t == 0) { soff = offs[n]; sdeg = offs[n + 1] - offs[n]; }
    __syncthreads();
    int off = soff, deg = sdeg;

    float acc = wself[n * Hh + h] * xp[(size_t)n * Dd + h * Cc + lane];
    for (int c0 = 0; c0 < deg; c0 += 128) {
        int cn = min(128, deg - c0);
        __syncthreads();
        if (t < cn) ssrc[t] = csrc[off + c0 + t];
        __syncthreads();
        for (int i = 0; i < cn; ++i) {
            int s = ssrc[i];
            float ww = w[(size_t)(off + c0 + i) * Hh + h];
            acc += ww * xp[(size_t)s * Dd + h * Cc + lane];
        }
    }

    float r = acc + bias[t] + m[(size_t)n * Dd + t];
    // LayerNorm over 256 threads
    float s = wred_sum(r);
    if (lane == 0) sh[h] = s;
    __syncthreads();
    if (t < 8) {
        float v = sh[t];
        #pragma unroll
        for (int o = 4; o; o >>= 1) v += __shfl_xor_sync(0xffu, v, o);
        if (t == 0) sh[32] = v;
    }
    __syncthreads();
    float mean = sh[32] * (1.0f / Dd);
    float dv = r - mean;
    float sq = wred_sum(dv * dv);
    if (lane == 0) sh[h] = sq;
    __syncthreads();
    if (t < 8) {
        float v = sh[t];
        #pragma unroll
        for (int o = 4; o; o >>= 1) v += __shfl_xor_sync(0xffu, v, o);
        if (t == 0) sh[33] = v;
    }
    __syncthreads();
    float var = sh[33] * (1.0f / Dd);
    out[(size_t)n * Dd + t] = dv * rsqrtf(var + 1e-5f) * gamma[t] + beta[t];
}

// LayerNorm over D=256 of (a + b); one block per row, 256 threads
__global__ void ln_kernel(const float* __restrict__ a, const float* __restrict__ b,
                          const float* __restrict__ gamma, const float* __restrict__ beta,
                          float* __restrict__ out) {
    int n = blockIdx.x;
    int t = threadIdx.x;
    int h = t >> 5, lane = t & 31;
    size_t off = (size_t)n * Dd + t;
    float r = a[off] + b[off];
    __shared__ float sh[40];
    float s = wred_sum(r);
    if (lane == 0) sh[h] = s;
    __syncthreads();
    if (t < 8) {
        float v = sh[t];
        #pragma unroll
        for (int o = 4; o; o >>= 1) v += __shfl_xor_sync(0xffu, v, o);
        if (t == 0) sh[32] = v;
    }
    __syncthreads();
    float mean = sh[32] * (1.0f / Dd);
    float dv = r - mean;
    float sq = wred_sum(dv * dv);
    if (lane == 0) sh[h] = sq;
    __syncthreads();
    if (t < 8) {
        float v = sh[t];
        #pragma unroll
        for (int o = 4; o; o >>= 1) v += __shfl_xor_sync(0xffu, v, o);
        if (t == 0) sh[33] = v;
    }
    __syncthreads();
    float var = sh[33] * (1.0f / Dd);
    out[off] = dv * rsqrtf(var + 1e-5f) * gamma[t] + beta[t];
}

// ---------------- SGEMM: C[M,N] = A[M,K] @ B[K,N] (+bias)(+relu) ----------------
template<bool BIAS, bool RELU>
__global__ void __launch_bounds__(256) sgemm128(int M, int N, int K,
                                                const float* __restrict__ A,
                                                const float* __restrict__ B,
                                                const float* __restrict__ bias,
                                                float* __restrict__ C) {
    const int BM = 128, BN = 128, BK = 8, TM = 8, TN = 8;
    __shared__ float As[BK * BM];
    __shared__ float Bs[BK * BN];
    int cRow = blockIdx.y, cCol = blockIdx.x;
    int tid = threadIdx.x;
    int threadCol = tid % (BN / TN);
    int threadRow = tid / (BN / TN);
    int innerRowA = tid >> 1;
    int innerColA = (tid & 1) * 4;
    int innerRowB = tid >> 5;
    int innerColB = (tid & 31) * 4;
    const float* Ab = A + (size_t)cRow * BM * K;
    const float* Bb = B + (size_t)cCol * BN;
    float* Cb = C + (size_t)cRow * BM * N + (size_t)cCol * BN;
    int aRowGlobal = cRow * BM + innerRowA;

    float acc[TM][TN] = {};
    float regM[TM], regN[TN];

    for (int k0 = 0; k0 < K; k0 += BK) {
        float4 av;
        if (aRowGlobal < M)
            av = *reinterpret_cast<const float4*>(Ab + (size_t)innerRowA * K + k0 + innerColA);
        else
            av = make_float4(0.f, 0.f, 0.f, 0.f);
        As[(innerColA + 0) * BM + innerRowA] = av.x;
        As[(innerColA + 1) * BM + innerRowA] = av.y;
        As[(innerColA + 2) * BM + innerRowA] = av.z;
        As[(innerColA + 3) * BM + innerRowA] = av.w;
        float4 bv = *reinterpret_cast<const float4*>(Bb + (size_t)(k0 + innerRowB) * N + innerColB);
        *reinterpret_cast<float4*>(&Bs[innerRowB * BN + innerColB]) = bv;
        __syncthreads();
        #pragma unroll
        for (int k = 0; k < BK; ++k) {
            #pragma unroll
            for (int i = 0; i < TM; ++i) regM[i] = As[k * BM + threadRow * TM + i];
            #pragma unroll
            for (int j = 0; j < TN; ++j) regN[j] = Bs[k * BN + threadCol * TN + j];
            #pragma unroll
            for (int i = 0; i < TM; ++i)
                #pragma unroll
                for (int j = 0; j < TN; ++j)
                    acc[i][j] += regM[i] * regN[j];
        }
        __syncthreads();
    }
    #pragma unroll
    for (int i = 0; i < TM; ++i) {
        int row = cRow * BM + threadRow * TM + i;
        if (row >= M) break;
        #pragma unroll
        for (int j = 0; j < TN; j += 4) {
            float4 v;
            v.x = acc[i][j]; v.y = acc[i][j + 1]; v.z = acc[i][j + 2]; v.w = acc[i][j + 3];
            if (BIAS) {
                int col = cCol * BN + threadCol * TN + j;
                v.x += bias[col]; v.y += bias[col + 1]; v.z += bias[col + 2]; v.w += bias[col + 3];
            }
            if (RELU) {
                v.x = fmaxf(v.x, 0.f); v.y = fmaxf(v.y, 0.f);
                v.z = fmaxf(v.z, 0.f); v.w = fmaxf(v.w, 0.f);
            }
            *reinterpret_cast<float4*>(Cb + (size_t)(threadRow * TM + i) * N + threadCol * TN + j) = v;
        }
    }
}

// ---------------- orchestration ----------------
static inline void* symaddr(const void* sym) {
    void* p = nullptr;
    cudaGetSymbolAddress(&p, sym);
    return p;
}

extern "C" void kernel_launch(void* const* d_in, const int* in_sizes, int n_in,
                              void* d_out, int out_size) {
    const float* x        = (const float*)d_in[0];
    const void*  ei       = d_in[1];
    const float* edge_attr= (const float*)d_in[2];
    const float* W        = (const float*)d_in[3];
    const float* att_src  = (const float*)d_in[4];
    const float* att_dst  = (const float*)d_in[5];
    const float* att_edge = (const float*)d_in[6];
    const float* W_edge   = (const float*)d_in[7];
    const float* bias     = (const float*)d_in[8];
    const float* ffn_w1   = (const float*)d_in[9];
    const float* ffn_b1   = (const float*)d_in[10];
    const float* ffn_w2   = (const float*)d_in[11];
    const float* ffn_b2   = (const float*)d_in[12];
    const float* ln1_g    = (const float*)d_in[13];
    const float* ln1_b    = (const float*)d_in[14];
    const float* ln2_g    = (const float*)d_in[15];
    const float* ln2_b    = (const float*)d_in[16];
    float* out = (float*)d_out;

    float* pm     = (float*)symaddr(g_m);
    float* pxp    = (float*)symaddr(g_xp);
    float* pm1    = (float*)symaddr(g_m1);
    float* ph     = (float*)symaddr(g_hbuf);
    float* ph2    = (float*)symaddr(g_h2);
    float* pw     = (float*)symaddr(g_w);
    float* pwself = (float*)symaddr(g_wself);
    float* paedge = (float*)symaddr(g_aedge);
    float* pasrc  = (float*)symaddr(g_asrc);
    float* padst  = (float*)symaddr(g_adst);
    float* peasum = (float*)symaddr(g_easum);
    float* peamean= (float*)symaddr(g_eamean);
    float* pv     = (float*)symaddr(g_v);
    int*   psrc   = (int*)symaddr(g_src32);
    int*   pdst   = (int*)symaddr(g_dst32);
    int*   pdegi  = (int*)symaddr(g_degi);
    int*   poffs  = (int*)symaddr(g_offs);
    int*   pcur   = (int*)symaddr(g_cursor);
    int*   pcsrc  = (int*)symaddr(g_csrc);
    int*   pposof = (int*)symaddr(g_posof);

    const int T = 256;
    auto blk = [](long long n, int t) { return (unsigned)((n + t - 1) / t); };

    // ---- one-time (per launch) precompute ----
    zeroi_kernel<<<blk(Nn, T), T>>>(pdegi, Nn);
    zerof_kernel<<<blk((long long)Nn * EDd, T), T>>>(peasum, Nn * EDd);
    convert_idx_kernel<<<blk(Ee, T), T>>>(ei, psrc, pdst, pdegi);
    scan_kernel<<<1, 256>>>(pdegi, poffs, pcur);
    scatter_kernel<<<blk(Ee, T), T>>>(psrc, pdst, pcur, pcsrc, pposof);
    easum_kernel<<<blk((long long)Ee * EDd, T), T>>>(pdst, edge_attr, peasum);
    eamean_kernel<<<blk((long long)Nn * EDd, T), T>>>(peasum, pdegi, peamean);
    v_kernel<<<1, 128>>>(W_edge, att_edge, pv);
    aedge_kernel<<<blk((long long)(Ee + Nn), T), T>>>(edge_attr, peamean, pv, pposof, paedge);
    copy_kernel<<<blk((long long)Nn * Dd, T), T>>>(pm, x, Nn * Dd);

    dim3 gProj(Dd / 128, (Nn + 127) / 128);
    dim3 gF1(D4 / 128, (Nn + 127) / 128);
    dim3 gF2(Dd / 128, (Nn + 127) / 128);
    unsigned gW = blk((long long)Nn * Hh * 32, T);   // warp-per-(n,h) kernels

    for (int i = 0; i < Ll; ++i) {
        sgemm128<false, false><<<gProj, 256>>>(Nn, Dd, Dd, pm, W, nullptr, pxp);
        asrc_adst_kernel<<<gW, T>>>(pxp, att_src, att_dst, pasrc, padst);
        attw_kernel<<<gW, T>>>(poffs, pcsrc, pasrc, padst, paedge, pw, pwself);
        agg_ln1_kernel<<<Nn, 256>>>(poffs, pcsrc, pw, pwself, pxp, pm, bias,
                                    ln1_g + i * Dd, ln1_b + i * Dd, pm1);
        sgemm128<true, true><<<gF1, 256>>>(Nn, D4, Dd, pm1,
                                           ffn_w1 + (size_t)i * Dd * D4, ffn_b1 + (size_t)i * D4, ph);
        sgemm128<true, false><<<gF2, 256>>>(Nn, Dd, D4, ph,
                                            ffn_w2 + (size_t)i * D4 * Dd, ffn_b2 + (size_t)i * Dd, ph2);
        float* lnout = (i == Ll - 1) ? out : pm;
        ln_kernel<<<Nn, 256>>>(ph2, pm1, ln2_g + i * Dd, ln2_b + i * Dd, lnout);
    }
}

// round 4
// speedup vs baseline: 2.0553x; 1.4506x over previous
#include <cuda_runtime.h>
#include <cuda_bf16.h>

// Problem constants (fixed shapes per reference)
#define Nn 50000
#define Ee 800000
#define Dd 256
#define Hh 8
#define Cc 32
#define EDd 16
#define Ll 6
#define D4 (4*Dd)

// ---------------- device scratch ----------------
__device__ float    g_m    [Nn*Dd];
__device__ float    g_xp   [Nn*Dd];
__device__ float    g_m1   [Nn*Dd];
__device__ float    g_hbuf [Nn*D4];
__device__ float    g_h2   [Nn*Dd];
__device__ float    g_w    [Ee*Hh];
__device__ float    g_wself[Nn*Hh];
__device__ float    g_aedge[(Ee+Nn)*Hh];
__device__ float    g_asrc [Nn*Hh];
__device__ float    g_adst [Nn*Hh];
__device__ float    g_easum[Nn*EDd];
__device__ float    g_eamean[Nn*EDd];
__device__ float    g_v    [EDd*Hh];
__device__ int      g_src32[Ee];
__device__ int      g_dst32[Ee];
__device__ int      g_degi [Nn];
__device__ int      g_offs [Nn+1];
__device__ int      g_cursor[Nn];
__device__ int      g_csrc [Ee];
__device__ int      g_posof[Ee];
// pre-split, pre-transposed weights (bf16 hi/lo, [N][K] layout)
__device__ __nv_bfloat16 g_Whi [Dd*Dd],   g_Wlo [Dd*Dd];
__device__ __nv_bfloat16 g_w1hi[Ll*Dd*D4], g_w1lo[Ll*Dd*D4];
__device__ __nv_bfloat16 g_w2hi[Ll*D4*Dd], g_w2lo[Ll*D4*Dd];

__device__ __forceinline__ float lrelu(float x) { return x > 0.f ? x : 0.2f * x; }
__device__ __forceinline__ int clampN(int v) { return v < 0 ? 0 : (v >= Nn ? Nn - 1 : v); }
__device__ __forceinline__ float wred_max(float v) {
    #pragma unroll
    for (int o = 16; o; o >>= 1) v = fmaxf(v, __shfl_xor_sync(0xffffffffu, v, o));
    return v;
}
__device__ __forceinline__ float wred_sum(float v) {
    #pragma unroll
    for (int o = 16; o; o >>= 1) v += __shfl_xor_sync(0xffffffffu, v, o);
    return v;
}

// ---------------- index conversion with on-device dtype detection ----------------
__global__ void convert_idx_kernel(const void* eiraw, int* src32, int* dst32, int* degi) {
    const long long* ei64 = (const long long*)eiraw;
    bool is64 = true;
    #pragma unroll
    for (int k = 0; k < 8; ++k) {
        unsigned long long v = (unsigned long long)ei64[k];
        if (v >= (unsigned long long)Nn) is64 = false;
    }
    int e = blockIdx.x * blockDim.x + threadIdx.x;
    if (e >= Ee) return;
    int s, d;
    if (is64) { s = (int)ei64[e]; d = (int)ei64[e + Ee]; }
    else      { const int* ei32 = (const int*)eiraw; s = ei32[e]; d = ei32[e + Ee]; }
    s = clampN(s); d = clampN(d);
    src32[e] = s;
    dst32[e] = d;
    atomicAdd(&degi[d], 1);
}

// ---------------- small utility kernels ----------------
__global__ void copy_kernel(float* __restrict__ dst, const float* __restrict__ src, int n) {
    int i = blockIdx.x * blockDim.x + threadIdx.x;
    if (i < n) dst[i] = src[i];
}
__global__ void zerof_kernel(float* __restrict__ p, int n) {
    int i = blockIdx.x * blockDim.x + threadIdx.x;
    if (i < n) p[i] = 0.f;
}
__global__ void zeroi_kernel(int* __restrict__ p, int n) {
    int i = blockIdx.x * blockDim.x + threadIdx.x;
    if (i < n) p[i] = 0;
}

// split fp32 weight [K][N] into bf16 hi/lo transposed [N][K]
__global__ void splitT_kernel(const float* __restrict__ Wsrc, int K, int N,
                              __nv_bfloat16* __restrict__ hi, __nv_bfloat16* __restrict__ lo) {
    int idx = blockIdx.x * blockDim.x + threadIdx.x;
    if (idx >= K * N) return;
    int k = idx / N, n = idx - k * N;
    float v = Wsrc[idx];
    __nv_bfloat16 h = __float2bfloat16(v);
    __nv_bfloat16 l = __float2bfloat16(v - __bfloat162float(h));
    hi[(size_t)n * K + k] = h;
    lo[(size_t)n * K + k] = l;
}

// single-block exclusive scan of degrees -> offsets + cursor copy
__global__ void scan_kernel(const int* __restrict__ degi, int* __restrict__ offs,
                            int* __restrict__ cursor) {
    __shared__ int part[256];
    int t = threadIdx.x;
    const int CH = (Nn + 255) / 256;
    int s = 0;
    for (int i = 0; i < CH; ++i) {
        int idx = t * CH + i;
        if (idx < Nn) s += degi[idx];
    }
    part[t] = s;
    __syncthreads();
    if (t == 0) {
        int acc = 0;
        for (int i = 0; i < 256; ++i) { int v = part[i]; part[i] = acc; acc += v; }
    }
    __syncthreads();
    int run = part[t];
    for (int i = 0; i < CH; ++i) {
        int idx = t * CH + i;
        if (idx < Nn) {
            offs[idx] = run;
            cursor[idx] = run;
            run += degi[idx];
        }
    }
    if (t == 0) offs[Nn] = Ee;
}

// scatter edges into CSR order
__global__ void scatter_kernel(const int* __restrict__ src, const int* __restrict__ dst,
                               int* __restrict__ cursor, int* __restrict__ csrc,
                               int* __restrict__ posof) {
    int e = blockIdx.x * blockDim.x + threadIdx.x;
    if (e >= Ee) return;
    int d = dst[e];
    int p = atomicAdd(&cursor[d], 1);
    csrc[p] = src[e];
    posof[e] = p;
}

__global__ void easum_kernel(const int* __restrict__ dst, const float* __restrict__ ea,
                             float* __restrict__ easum) {
    int idx = blockIdx.x * blockDim.x + threadIdx.x;
    if (idx >= Ee * EDd) return;
    int e = idx >> 4, j = idx & 15;
    atomicAdd(&easum[dst[e] * EDd + j], ea[idx]);
}
__global__ void eamean_kernel(const float* __restrict__ easum, const int* __restrict__ degi,
                              float* __restrict__ eamean) {
    int idx = blockIdx.x * blockDim.x + threadIdx.x;
    if (idx >= Nn * EDd) return;
    int n = idx >> 4;
    eamean[idx] = easum[idx] / fmaxf((float)degi[n], 1.0f);
}
__global__ void v_kernel(const float* __restrict__ W_edge, const float* __restrict__ att_edge,
                         float* __restrict__ v) {
    int t = threadIdx.x;
    if (t >= EDd * Hh) return;
    int d = t >> 3, h = t & 7;
    float s = 0.f;
    #pragma unroll
    for (int c = 0; c < Cc; ++c) s += W_edge[d * Dd + h * Cc + c] * att_edge[h * Cc + c];
    v[d * Hh + h] = s;
}
__global__ void aedge_kernel(const float* __restrict__ ea, const float* __restrict__ eamean,
                             const float* __restrict__ v, const int* __restrict__ posof,
                             float* __restrict__ aedge) {
    int e = blockIdx.x * blockDim.x + threadIdx.x;
    if (e >= Ee + Nn) return;
    const float* p = (e < Ee) ? (ea + (size_t)e * EDd) : (eamean + (size_t)(e - Ee) * EDd);
    float r[EDd];
    #pragma unroll
    for (int j = 0; j < EDd; ++j) r[j] = p[j];
    size_t row = (e < Ee) ? (size_t)posof[e] : (size_t)e;
    #pragma unroll
    for (int h = 0; h < Hh; ++h) {
        float s = 0.f;
        #pragma unroll
        for (int j = 0; j < EDd; ++j) s += r[j] * v[j * Hh + h];
        aedge[row * Hh + h] = s;
    }
}

// warp per (node, head): a_src and a_dst dot products
__global__ void asrc_adst_kernel(const float* __restrict__ xp,
                                 const float* __restrict__ att_src,
                                 const float* __restrict__ att_dst,
                                 float* __restrict__ asrc, float* __restrict__ adst) {
    int gw = (blockIdx.x * blockDim.x + threadIdx.x) >> 5;
    int lane = threadIdx.x & 31;
    if (gw >= Nn * Hh) return;
    int n = gw >> 3, h = gw & 7;
    float v = xp[(size_t)n * Dd + h * Cc + lane];
    float s = wred_sum(v * att_src[h * Cc + lane]);
    float d = wred_sum(v * att_dst[h * Cc + lane]);
    if (lane == 0) { asrc[gw] = s; adst[gw] = d; }
}

// warp per (node, head): softmax over incoming edges (CSR)
__global__ void attw_kernel(const int* __restrict__ offs, const int* __restrict__ csrc,
                            const float* __restrict__ asrc, const float* __restrict__ adst,
                            const float* __restrict__ aedge,
                            float* __restrict__ w, float* __restrict__ wself) {
    int gw = (blockIdx.x * blockDim.x + threadIdx.x) >> 5;
    int lane = threadIdx.x & 31;
    if (gw >= Nn * Hh) return;
    int n = gw >> 3, h = gw & 7;
    int off = offs[n];
    int deg = offs[n + 1] - off;
    float adstn = adst[gw];
    float al_self = lrelu(asrc[gw] + adstn + aedge[(size_t)(Ee + n) * Hh + h]);

    if (deg <= 32) {
        float al = -3.4e38f;
        if (lane < deg) {
            int s = csrc[off + lane];
            al = lrelu(asrc[s * Hh + h] + adstn + aedge[(size_t)(off + lane) * Hh + h]);
        }
        float M = fmaxf(al_self, wred_max(al));
        float ex = (lane < deg) ? expf(al - M) : 0.f;
        float exs = expf(al_self - M);
        float denom = exs + wred_sum(ex);
        if (lane < deg) w[(size_t)(off + lane) * Hh + h] = ex / denom;
        if (lane == 0) wself[gw] = exs / denom;
    } else {
        float M = al_self;
        for (int i = lane; i < deg; i += 32) {
            int s = csrc[off + i];
            float al = lrelu(asrc[s * Hh + h] + adstn + aedge[(size_t)(off + i) * Hh + h]);
            w[(size_t)(off + i) * Hh + h] = al;
            M = fmaxf(M, al);
        }
        M = wred_max(M);
        float sum = 0.f;
        for (int i = lane; i < deg; i += 32) {
            float ex = expf(w[(size_t)(off + i) * Hh + h] - M);
            w[(size_t)(off + i) * Hh + h] = ex;
            sum += ex;
        }
        float exs = expf(al_self - M);
        float denom = exs + wred_sum(sum);
        float inv = 1.f / denom;
        for (int i = lane; i < deg; i += 32) w[(size_t)(off + i) * Hh + h] *= inv;
        if (lane == 0) wself[gw] = exs * inv;
    }
}

// block per node: gather-aggregate + bias + residual + LayerNorm1 (fused)
__global__ void __launch_bounds__(256) agg_ln1_kernel(
        const int* __restrict__ offs, const int* __restrict__ csrc,
        const float* __restrict__ w, const float* __restrict__ wself,
        const float* __restrict__ xp, const float* __restrict__ m,
        const float* __restrict__ bias,
        const float* __restrict__ gamma, const float* __restrict__ beta,
        float* __restrict__ out) {
    int n = blockIdx.x;
    int t = threadIdx.x;
    int h = t >> 5, lane = t & 31;
    __shared__ int ssrc[128];
    __shared__ float sh[40];
    __shared__ int soff, sdeg;
    if (t == 0) { soff = offs[n]; sdeg = offs[n + 1] - offs[n]; }
    __syncthreads();
    int off = soff, deg = sdeg;

    float acc = wself[n * Hh + h] * xp[(size_t)n * Dd + h * Cc + lane];
    for (int c0 = 0; c0 < deg; c0 += 128) {
        int cn = min(128, deg - c0);
        __syncthreads();
        if (t < cn) ssrc[t] = csrc[off + c0 + t];
        __syncthreads();
        for (int i = 0; i < cn; ++i) {
            int s = ssrc[i];
            float ww = w[(size_t)(off + c0 + i) * Hh + h];
            acc += ww * xp[(size_t)s * Dd + h * Cc + lane];
        }
    }

    float r = acc + bias[t] + m[(size_t)n * Dd + t];
    float s = wred_sum(r);
    if (lane == 0) sh[h] = s;
    __syncthreads();
    if (t < 8) {
        float v = sh[t];
        #pragma unroll
        for (int o = 4; o; o >>= 1) v += __shfl_xor_sync(0xffu, v, o);
        if (t == 0) sh[32] = v;
    }
    __syncthreads();
    float mean = sh[32] * (1.0f / Dd);
    float dv = r - mean;
    float sq = wred_sum(dv * dv);
    if (lane == 0) sh[h] = sq;
    __syncthreads();
    if (t < 8) {
        float v = sh[t];
        #pragma unroll
        for (int o = 4; o; o >>= 1) v += __shfl_xor_sync(0xffu, v, o);
        if (t == 0) sh[33] = v;
    }
    __syncthreads();
    float var = sh[33] * (1.0f / Dd);
    out[(size_t)n * Dd + t] = dv * rsqrtf(var + 1e-5f) * gamma[t] + beta[t];
}

// LayerNorm over D=256 of (a + b)
__global__ void ln_kernel(const float* __restrict__ a, const float* __restrict__ b,
                          const float* __restrict__ gamma, const float* __restrict__ beta,
                          float* __restrict__ out) {
    int n = blockIdx.x;
    int t = threadIdx.x;
    int h = t >> 5, lane = t & 31;
    size_t off = (size_t)n * Dd + t;
    float r = a[off] + b[off];
    __shared__ float sh[40];
    float s = wred_sum(r);
    if (lane == 0) sh[h] = s;
    __syncthreads();
    if (t < 8) {
        float v = sh[t];
        #pragma unroll
        for (int o = 4; o; o >>= 1) v += __shfl_xor_sync(0xffu, v, o);
        if (t == 0) sh[32] = v;
    }
    __syncthreads();
    float mean = sh[32] * (1.0f / Dd);
    float dv = r - mean;
    float sq = wred_sum(dv * dv);
    if (lane == 0) sh[h] = sq;
    __syncthreads();
    if (t < 8) {
        float v = sh[t];
        #pragma unroll
        for (int o = 4; o; o >>= 1) v += __shfl_xor_sync(0xffu, v, o);
        if (t == 0) sh[33] = v;
    }
    __syncthreads();
    float var = sh[33] * (1.0f / Dd);
    out[off] = dv * rsqrtf(var + 1e-5f) * gamma[t] + beta[t];
}

// ---------------- tensor-core GEMM (split-bf16, 2-term) ----------------
// C[M,N] = A[M,K] @ B[K,N]; A fp32 (split on the fly), B pre-split bf16 hi/lo stored [N][K].
__device__ __forceinline__ void mma_bf16(float& d0, float& d1, float& d2, float& d3,
                                         unsigned a0, unsigned a1, unsigned a2, unsigned a3,
                                         unsigned b0, unsigned b1) {
    asm volatile("mma.sync.aligned.m16n8k16.row.col.f32.bf16.bf16.f32 "
                 "{%0,%1,%2,%3}, {%4,%5,%6,%7}, {%8,%9}, {%0,%1,%2,%3};\n"
                 : "+f"(d0), "+f"(d1), "+f"(d2), "+f"(d3)
                 : "r"(a0), "r"(a1), "r"(a2), "r"(a3), "r"(b0), "r"(b1));
}

template<bool BIAS, bool RELU>
__global__ void __launch_bounds__(256) gemm_tc(int M, int N, int K,
        const float* __restrict__ A,
        const __nv_bfloat16* __restrict__ Bhi, const __nv_bfloat16* __restrict__ Blo,
        const float* __restrict__ bias, float* __restrict__ C) {
    const int BM = 128, BN = 128, BK = 32, KP = 40;
    __shared__ __align__(16) __nv_bfloat16 Ah[BM * KP];
    __shared__ __align__(16) __nv_bfloat16 Al[BM * KP];
    __shared__ __align__(16) __nv_bfloat16 Bh[BN * KP];
    __shared__ __align__(16) __nv_bfloat16 Bl[BN * KP];
    int tid = threadIdx.x;
    int bm0 = blockIdx.y * BM, bn0 = blockIdx.x * BN;
    int w = tid >> 5, lane = tid & 31;
    int wm = w & 1, wn = w >> 1;           // 2 x 4 warp grid -> warp tile 64(M) x 32(N)
    int g = lane >> 2, tig = lane & 3;

    float acc[4][4][4];
    #pragma unroll
    for (int i = 0; i < 4; ++i)
        #pragma unroll
        for (int j = 0; j < 4; ++j)
            #pragma unroll
            for (int q = 0; q < 4; ++q) acc[i][j][q] = 0.f;

    int lr = tid >> 3;            // 0..31
    int lk = (tid & 7) * 4;       // 0,4,...,28

    for (int k0 = 0; k0 < K; k0 += BK) {
        // load + split A tile (128x32 f32)
        #pragma unroll
        for (int p = 0; p < 4; ++p) {
            int r = p * 32 + lr;
            int grow = bm0 + r;
            float4 v;
            if (grow < M) v = *reinterpret_cast<const float4*>(A + (size_t)grow * K + k0 + lk);
            else          v = make_float4(0.f, 0.f, 0.f, 0.f);
            __nv_bfloat16 h0 = __float2bfloat16(v.x), h1 = __float2bfloat16(v.y);
            __nv_bfloat16 h2 = __float2bfloat16(v.z), h3 = __float2bfloat16(v.w);
            __nv_bfloat16 l0 = __float2bfloat16(v.x - __bfloat162float(h0));
            __nv_bfloat16 l1 = __float2bfloat16(v.y - __bfloat162float(h1));
            __nv_bfloat16 l2 = __float2bfloat16(v.z - __bfloat162float(h2));
            __nv_bfloat16 l3 = __float2bfloat16(v.w - __bfloat162float(h3));
            __nv_bfloat162 ph01 = __nv_bfloat162(h0, h1), ph23 = __nv_bfloat162(h2, h3);
            __nv_bfloat162 pl01 = __nv_bfloat162(l0, l1), pl23 = __nv_bfloat162(l2, l3);
            uint2 uh, ul;
            uh.x = *reinterpret_cast<unsigned*>(&ph01);
            uh.y = *reinterpret_cast<unsigned*>(&ph23);
            ul.x = *reinterpret_cast<unsigned*>(&pl01);
            ul.y = *reinterpret_cast<unsigned*>(&pl23);
            *reinterpret_cast<uint2*>(&Ah[r * KP + lk]) = uh;
            *reinterpret_cast<uint2*>(&Al[r * KP + lk]) = ul;
        }
        // load B tile (128 n-rows x 32 k), already bf16 [N][K]
        #pragma unroll
        for (int p = 0; p < 4; ++p) {
            int r = p * 32 + lr;
            size_t goff = (size_t)(bn0 + r) * K + k0 + lk;
            *reinterpret_cast<uint2*>(&Bh[r * KP + lk]) =
                *reinterpret_cast<const uint2*>(Bhi + goff);
            *reinterpret_cast<uint2*>(&Bl[r * KP + lk]) =
                *reinterpret_cast<const uint2*>(Blo + goff);
        }
        __syncthreads();

        #pragma unroll
        for (int kk = 0; kk < BK; kk += 16) {
            unsigned afh[4][4], afl[4][4], bfh[4][2], bfl[4][2];
            #pragma unroll
            for (int mt = 0; mt < 4; ++mt) {
                int r0 = wm * 64 + mt * 16 + g;
                int base = kk + 2 * tig;
                afh[mt][0] = *reinterpret_cast<unsigned*>(&Ah[r0 * KP + base]);
                afh[mt][1] = *reinterpret_cast<unsigned*>(&Ah[(r0 + 8) * KP + base]);
                afh[mt][2] = *reinterpret_cast<unsigned*>(&Ah[r0 * KP + base + 8]);
                afh[mt][3] = *reinterpret_cast<unsigned*>(&Ah[(r0 + 8) * KP + base + 8]);
                afl[mt][0] = *reinterpret_cast<unsigned*>(&Al[r0 * KP + base]);
                afl[mt][1] = *reinterpret_cast<unsigned*>(&Al[(r0 + 8) * KP + base]);
                afl[mt][2] = *reinterpret_cast<unsigned*>(&Al[r0 * KP + base + 8]);
                afl[mt][3] = *reinterpret_cast<unsigned*>(&Al[(r0 + 8) * KP + base + 8]);
            }
            #pragma unroll
            for (int nt = 0; nt < 4; ++nt) {
                int c0 = wn * 32 + nt * 8 + g;
                int base = kk + 2 * tig;
                bfh[nt][0] = *reinterpret_cast<unsigned*>(&Bh[c0 * KP + base]);
                bfh[nt][1] = *reinterpret_cast<unsigned*>(&Bh[c0 * KP + base + 8]);
                bfl[nt][0] = *reinterpret_cast<unsigned*>(&Bl[c0 * KP + base]);
                bfl[nt][1] = *reinterpret_cast<unsigned*>(&Bl[c0 * KP + base + 8]);
            }
            #pragma unroll
            for (int mt = 0; mt < 4; ++mt)
                #pragma unroll
                for (int nt = 0; nt < 4; ++nt) {
                    mma_bf16(acc[mt][nt][0], acc[mt][nt][1], acc[mt][nt][2], acc[mt][nt][3],
                             afh[mt][0], afh[mt][1], afh[mt][2], afh[mt][3],
                             bfh[nt][0], bfh[nt][1]);
                    mma_bf16(acc[mt][nt][0], acc[mt][nt][1], acc[mt][nt][2], acc[mt][nt][3],
                             afh[mt][0], afh[mt][1], afh[mt][2], afh[mt][3],
                             bfl[nt][0], bfl[nt][1]);
                    mma_bf16(acc[mt][nt][0], acc[mt][nt][1], acc[mt][nt][2], acc[mt][nt][3],
                             afl[mt][0], afl[mt][1], afl[mt][2], afl[mt][3],
                             bfh[nt][0], bfh[nt][1]);
                }
        }
        __syncthreads();
    }

    // epilogue
    #pragma unroll
    for (int mt = 0; mt < 4; ++mt) {
        #pragma unroll
        for (int half = 0; half < 2; ++half) {
            int row = bm0 + wm * 64 + mt * 16 + g + half * 8;
            if (row < M) {
                #pragma unroll
                for (int nt = 0; nt < 4; ++nt) {
                    int col = bn0 + wn * 32 + nt * 8 + 2 * tig;
                    float2 v;
                    v.x = acc[mt][nt][half * 2 + 0];
                    v.y = acc[mt][nt][half * 2 + 1];
                    if (BIAS) { v.x += bias[col]; v.y += bias[col + 1]; }
                    if (RELU) { v.x = fmaxf(v.x, 0.f); v.y = fmaxf(v.y, 0.f); }
                    *reinterpret_cast<float2*>(C + (size_t)row * N + col) = v;
                }
            }
        }
    }
}

// ---------------- orchestration ----------------
static inline void* symaddr(const void* sym) {
    void* p = nullptr;
    cudaGetSymbolAddress(&p, sym);
    return p;
}

extern "C" void kernel_launch(void* const* d_in, const int* in_sizes, int n_in,
                              void* d_out, int out_size) {
    const float* x        = (const float*)d_in[0];
    const void*  ei       = d_in[1];
    const float* edge_attr= (const float*)d_in[2];
    const float* W        = (const float*)d_in[3];
    const float* att_src  = (const float*)d_in[4];
    const float* att_dst  = (const float*)d_in[5];
    const float* att_edge = (const float*)d_in[6];
    const float* W_edge   = (const float*)d_in[7];
    const float* bias     = (const float*)d_in[8];
    const float* ffn_w1   = (const float*)d_in[9];
    const float* ffn_b1   = (const float*)d_in[10];
    const float* ffn_w2   = (const float*)d_in[11];
    const float* ffn_b2   = (const float*)d_in[12];
    const float* ln1_g    = (const float*)d_in[13];
    const float* ln1_b    = (const float*)d_in[14];
    const float* ln2_g    = (const float*)d_in[15];
    const float* ln2_b    = (const float*)d_in[16];
    float* out = (float*)d_out;

    float* pm     = (float*)symaddr(g_m);
    float* pxp    = (float*)symaddr(g_xp);
    float* pm1    = (float*)symaddr(g_m1);
    float* ph     = (float*)symaddr(g_hbuf);
    float* ph2    = (float*)symaddr(g_h2);
    float* pw     = (float*)symaddr(g_w);
    float* pwself = (float*)symaddr(g_wself);
    float* paedge = (float*)symaddr(g_aedge);
    float* pasrc  = (float*)symaddr(g_asrc);
    float* padst  = (float*)symaddr(g_adst);
    float* peasum = (float*)symaddr(g_easum);
    float* peamean= (float*)symaddr(g_eamean);
    float* pv     = (float*)symaddr(g_v);
    int*   psrc   = (int*)symaddr(g_src32);
    int*   pdst   = (int*)symaddr(g_dst32);
    int*   pdegi  = (int*)symaddr(g_degi);
    int*   poffs  = (int*)symaddr(g_offs);
    int*   pcur   = (int*)symaddr(g_cursor);
    int*   pcsrc  = (int*)symaddr(g_csrc);
    int*   pposof = (int*)symaddr(g_posof);
    __nv_bfloat16* pWhi  = (__nv_bfloat16*)symaddr(g_Whi);
    __nv_bfloat16* pWlo  = (__nv_bfloat16*)symaddr(g_Wlo);
    __nv_bfloat16* pw1hi = (__nv_bfloat16*)symaddr(g_w1hi);
    __nv_bfloat16* pw1lo = (__nv_bfloat16*)symaddr(g_w1lo);
    __nv_bfloat16* pw2hi = (__nv_bfloat16*)symaddr(g_w2hi);
    __nv_bfloat16* pw2lo = (__nv_bfloat16*)symaddr(g_w2lo);

    const int T = 256;
    auto blk = [](long long n, int t) { return (unsigned)((n + t - 1) / t); };

    // ---- one-time precompute ----
    zeroi_kernel<<<blk(Nn, T), T>>>(pdegi, Nn);
    zerof_kernel<<<blk((long long)Nn * EDd, T), T>>>(peasum, Nn * EDd);
    convert_idx_kernel<<<blk(Ee, T), T>>>(ei, psrc, pdst, pdegi);
    scan_kernel<<<1, 256>>>(pdegi, poffs, pcur);
    scatter_kernel<<<blk(Ee, T), T>>>(psrc, pdst, pcur, pcsrc, pposof);
    easum_kernel<<<blk((long long)Ee * EDd, T), T>>>(pdst, edge_attr, peasum);
    eamean_kernel<<<blk((long long)Nn * EDd, T), T>>>(peasum, pdegi, peamean);
    v_kernel<<<1, 128>>>(W_edge, att_edge, pv);
    aedge_kernel<<<blk((long long)(Ee + Nn), T), T>>>(edge_attr, peamean, pv, pposof, paedge);
    copy_kernel<<<blk((long long)Nn * Dd, T), T>>>(pm, x, Nn * Dd);

    // weight pre-split (transposed bf16 hi/lo)
    splitT_kernel<<<blk((long long)Dd * Dd, T), T>>>(W, Dd, Dd, pWhi, pWlo);
    for (int i = 0; i < Ll; ++i) {
        splitT_kernel<<<blk((long long)Dd * D4, T), T>>>(
            ffn_w1 + (size_t)i * Dd * D4, Dd, D4,
            pw1hi + (size_t)i * Dd * D4, pw1lo + (size_t)i * Dd * D4);
        splitT_kernel<<<blk((long long)D4 * Dd, T), T>>>(
            ffn_w2 + (size_t)i * D4 * Dd, D4, Dd,
            pw2hi + (size_t)i * D4 * Dd, pw2lo + (size_t)i * D4 * Dd);
    }

    dim3 gProj(Dd / 128, (Nn + 127) / 128);
    dim3 gF1(D4 / 128, (Nn + 127) / 128);
    dim3 gF2(Dd / 128, (Nn + 127) / 128);
    unsigned gW = blk((long long)Nn * Hh * 32, T);

    for (int i = 0; i < Ll; ++i) {
        gemm_tc<false, false><<<gProj, 256>>>(Nn, Dd, Dd, pm, pWhi, pWlo, nullptr, pxp);
        asrc_adst_kernel<<<gW, T>>>(pxp, att_src, att_dst, pasrc, padst);
        attw_kernel<<<gW, T>>>(poffs, pcsrc, pasrc, padst, paedge, pw, pwself);
        agg_ln1_kernel<<<Nn, 256>>>(poffs, pcsrc, pw, pwself, pxp, pm, bias,
                                    ln1_g + i * Dd, ln1_b + i * Dd, pm1);
        gemm_tc<true, true><<<gF1, 256>>>(Nn, D4, Dd, pm1,
                                          pw1hi + (size_t)i * Dd * D4, pw1lo + (size_t)i * Dd * D4,
                                          ffn_b1 + (size_t)i * D4, ph);
        gemm_tc<true, false><<<gF2, 256>>>(Nn, Dd, D4, ph,
                                           pw2hi + (size_t)i * D4 * Dd, pw2lo + (size_t)i * D4 * Dd,
                                           ffn_b2 + (size_t)i * Dd, ph2);
        float* lnout = (i == Ll - 1) ? out : pm;
        ln_kernel<<<Nn, 256>>>(ph2, pm1, ln2_g + i * Dd, ln2_b + i * Dd, lnout);
    }
}

// round 5
// speedup vs baseline: 2.4775x; 1.2054x over previous
#include <cuda_runtime.h>
#include <cuda_bf16.h>

// Problem constants (fixed shapes per reference)
#define Nn 50000
#define Ee 800000
#define Dd 256
#define Hh 8
#define Cc 32
#define EDd 16
#define Ll 6
#define D4 (4*Dd)

typedef __nv_bfloat16 bf16;
typedef __nv_bfloat162 bf162;

// ---------------- device scratch ----------------
__device__ float    g_m    [Nn*Dd];
__device__ bf16     g_mhi  [Nn*Dd],  g_mlo  [Nn*Dd];
__device__ float    g_xp   [Nn*Dd];
__device__ float    g_m1   [Nn*Dd];
__device__ bf16     g_m1hi [Nn*Dd],  g_m1lo [Nn*Dd];
__device__ bf16     g_hhi  [Nn*D4],  g_hlo  [Nn*D4];
__device__ float    g_h2   [Nn*Dd];
__device__ float    g_w    [Ee*Hh];
__device__ float    g_wself[Nn*Hh];
__device__ float    g_aedge[(Ee+Nn)*Hh];
__device__ float    g_asrc [Nn*Hh];
__device__ float    g_adst [Nn*Hh];
__device__ float    g_easum[Nn*EDd];
__device__ float    g_eamean[Nn*EDd];
__device__ float    g_v    [EDd*Hh];
__device__ int      g_src32[Ee];
__device__ int      g_dst32[Ee];
__device__ int      g_degi [Nn];
__device__ int      g_offs [Nn+1];
__device__ int      g_cursor[Nn];
__device__ int      g_csrc [Ee];
__device__ int      g_posof[Ee];
// pre-split, pre-transposed weights (bf16 hi/lo, [N][K] layout)
__device__ bf16 g_Whi [Dd*Dd],    g_Wlo [Dd*Dd];
__device__ bf16 g_w1hi[Ll*Dd*D4], g_w1lo[Ll*Dd*D4];
__device__ bf16 g_w2hi[Ll*D4*Dd], g_w2lo[Ll*D4*Dd];

__device__ __forceinline__ float lrelu(float x) { return x > 0.f ? x : 0.2f * x; }
__device__ __forceinline__ int clampN(int v) { return v < 0 ? 0 : (v >= Nn ? Nn - 1 : v); }
__device__ __forceinline__ float wred_max(float v) {
    #pragma unroll
    for (int o = 16; o; o >>= 1) v = fmaxf(v, __shfl_xor_sync(0xffffffffu, v, o));
    return v;
}
__device__ __forceinline__ float wred_sum(float v) {
    #pragma unroll
    for (int o = 16; o; o >>= 1) v += __shfl_xor_sync(0xffffffffu, v, o);
    return v;
}
__device__ __forceinline__ void split2(float x, bf16& h, bf16& l) {
    h = __float2bfloat16(x);
    l = __float2bfloat16(x - __bfloat162float(h));
}

// ---------------- index conversion with on-device dtype detection ----------------
__global__ void convert_idx_kernel(const void* eiraw, int* src32, int* dst32, int* degi) {
    const long long* ei64 = (const long long*)eiraw;
    bool is64 = true;
    #pragma unroll
    for (int k = 0; k < 8; ++k) {
        unsigned long long v = (unsigned long long)ei64[k];
        if (v >= (unsigned long long)Nn) is64 = false;
    }
    int e = blockIdx.x * blockDim.x + threadIdx.x;
    if (e >= Ee) return;
    int s, d;
    if (is64) { s = (int)ei64[e]; d = (int)ei64[e + Ee]; }
    else      { const int* ei32 = (const int*)eiraw; s = ei32[e]; d = ei32[e + Ee]; }
    s = clampN(s); d = clampN(d);
    src32[e] = s;
    dst32[e] = d;
    atomicAdd(&degi[d], 1);
}

// ---------------- small utility kernels ----------------
__global__ void split_act_kernel(const float* __restrict__ src, float* __restrict__ dstf,
                                 bf16* __restrict__ hi, bf16* __restrict__ lo, int n) {
    int i = blockIdx.x * blockDim.x + threadIdx.x;
    if (i >= n) return;
    float v = src[i];
    if (dstf) dstf[i] = v;
    bf16 h, l; split2(v, h, l);
    hi[i] = h; lo[i] = l;
}
__global__ void zerof_kernel(float* __restrict__ p, int n) {
    int i = blockIdx.x * blockDim.x + threadIdx.x;
    if (i < n) p[i] = 0.f;
}
__global__ void zeroi_kernel(int* __restrict__ p, int n) {
    int i = blockIdx.x * blockDim.x + threadIdx.x;
    if (i < n) p[i] = 0;
}

// split fp32 weight [K][N] into bf16 hi/lo transposed [N][K]
__global__ void splitT_kernel(const float* __restrict__ Wsrc, int K, int N,
                              bf16* __restrict__ hi, bf16* __restrict__ lo) {
    int idx = blockIdx.x * blockDim.x + threadIdx.x;
    if (idx >= K * N) return;
    int k = idx / N, n = idx - k * N;
    float v = Wsrc[idx];
    bf16 h, l; split2(v, h, l);
    hi[(size_t)n * K + k] = h;
    lo[(size_t)n * K + k] = l;
}

// single-block exclusive scan of degrees -> offsets + cursor copy
__global__ void scan_kernel(const int* __restrict__ degi, int* __restrict__ offs,
                            int* __restrict__ cursor) {
    __shared__ int part[256];
    int t = threadIdx.x;
    const int CH = (Nn + 255) / 256;
    int s = 0;
    for (int i = 0; i < CH; ++i) {
        int idx = t * CH + i;
        if (idx < Nn) s += degi[idx];
    }
    part[t] = s;
    __syncthreads();
    if (t == 0) {
        int acc = 0;
        for (int i = 0; i < 256; ++i) { int v = part[i]; part[i] = acc; acc += v; }
    }
    __syncthreads();
    int run = part[t];
    for (int i = 0; i < CH; ++i) {
        int idx = t * CH + i;
        if (idx < Nn) {
            offs[idx] = run;
            cursor[idx] = run;
            run += degi[idx];
        }
    }
    if (t == 0) offs[Nn] = Ee;
}

__global__ void scatter_kernel(const int* __restrict__ src, const int* __restrict__ dst,
                               int* __restrict__ cursor, int* __restrict__ csrc,
                               int* __restrict__ posof) {
    int e = blockIdx.x * blockDim.x + threadIdx.x;
    if (e >= Ee) return;
    int d = dst[e];
    int p = atomicAdd(&cursor[d], 1);
    csrc[p] = src[e];
    posof[e] = p;
}

__global__ void easum_kernel(const int* __restrict__ dst, const float* __restrict__ ea,
                             float* __restrict__ easum) {
    int idx = blockIdx.x * blockDim.x + threadIdx.x;
    if (idx >= Ee * EDd) return;
    int e = idx >> 4, j = idx & 15;
    atomicAdd(&easum[dst[e] * EDd + j], ea[idx]);
}
__global__ void eamean_kernel(const float* __restrict__ easum, const int* __restrict__ degi,
                              float* __restrict__ eamean) {
    int idx = blockIdx.x * blockDim.x + threadIdx.x;
    if (idx >= Nn * EDd) return;
    int n = idx >> 4;
    eamean[idx] = easum[idx] / fmaxf((float)degi[n], 1.0f);
}
__global__ void v_kernel(const float* __restrict__ W_edge, const float* __restrict__ att_edge,
                         float* __restrict__ v) {
    int t = threadIdx.x;
    if (t >= EDd * Hh) return;
    int d = t >> 3, h = t & 7;
    float s = 0.f;
    #pragma unroll
    for (int c = 0; c < Cc; ++c) s += W_edge[d * Dd + h * Cc + c] * att_edge[h * Cc + c];
    v[d * Hh + h] = s;
}
__global__ void aedge_kernel(const float* __restrict__ ea, const float* __restrict__ eamean,
                             const float* __restrict__ v, const int* __restrict__ posof,
                             float* __restrict__ aedge) {
    int e = blockIdx.x * blockDim.x + threadIdx.x;
    if (e >= Ee + Nn) return;
    const float* p = (e < Ee) ? (ea + (size_t)e * EDd) : (eamean + (size_t)(e - Ee) * EDd);
    float r[EDd];
    #pragma unroll
    for (int j = 0; j < EDd; ++j) r[j] = p[j];
    size_t row = (e < Ee) ? (size_t)posof[e] : (size_t)e;
    #pragma unroll
    for (int h = 0; h < Hh; ++h) {
        float s = 0.f;
        #pragma unroll
        for (int j = 0; j < EDd; ++j) s += r[j] * v[j * Hh + h];
        aedge[row * Hh + h] = s;
    }
}

// warp per (node, head): a_src and a_dst dot products
__global__ void asrc_adst_kernel(const float* __restrict__ xp,
                                 const float* __restrict__ att_src,
                                 const float* __restrict__ att_dst,
                                 float* __restrict__ asrc, float* __restrict__ adst) {
    int gw = (blockIdx.x * blockDim.x + threadIdx.x) >> 5;
    int lane = threadIdx.x & 31;
    if (gw >= Nn * Hh) return;
    int n = gw >> 3, h = gw & 7;
    float v = xp[(size_t)n * Dd + h * Cc + lane];
    float s = wred_sum(v * att_src[h * Cc + lane]);
    float d = wred_sum(v * att_dst[h * Cc + lane]);
    if (lane == 0) { asrc[gw] = s; adst[gw] = d; }
}

// warp per (node, head): softmax over incoming edges (CSR)
__global__ void attw_kernel(const int* __restrict__ offs, const int* __restrict__ csrc,
                            const float* __restrict__ asrc, const float* __restrict__ adst,
                            const float* __restrict__ aedge,
                            float* __restrict__ w, float* __restrict__ wself) {
    int gw = (blockIdx.x * blockDim.x + threadIdx.x) >> 5;
    int lane = threadIdx.x & 31;
    if (gw >= Nn * Hh) return;
    int n = gw >> 3, h = gw & 7;
    int off = offs[n];
    int deg = offs[n + 1] - off;
    float adstn = adst[gw];
    float al_self = lrelu(asrc[gw] + adstn + aedge[(size_t)(Ee + n) * Hh + h]);

    if (deg <= 32) {
        float al = -3.4e38f;
        if (lane < deg) {
            int s = csrc[off + lane];
            al = lrelu(asrc[s * Hh + h] + adstn + aedge[(size_t)(off + lane) * Hh + h]);
        }
        float M = fmaxf(al_self, wred_max(al));
        float ex = (lane < deg) ? expf(al - M) : 0.f;
        float exs = expf(al_self - M);
        float denom = exs + wred_sum(ex);
        if (lane < deg) w[(size_t)(off + lane) * Hh + h] = ex / denom;
        if (lane == 0) wself[gw] = exs / denom;
    } else {
        float M = al_self;
        for (int i = lane; i < deg; i += 32) {
            int s = csrc[off + i];
            float al = lrelu(asrc[s * Hh + h] + adstn + aedge[(size_t)(off + i) * Hh + h]);
            w[(size_t)(off + i) * Hh + h] = al;
            M = fmaxf(M, al);
        }
        M = wred_max(M);
        float sum = 0.f;
        for (int i = lane; i < deg; i += 32) {
            float ex = expf(w[(size_t)(off + i) * Hh + h] - M);
            w[(size_t)(off + i) * Hh + h] = ex;
            sum += ex;
        }
        float exs = expf(al_self - M);
        float denom = exs + wred_sum(sum);
        float inv = 1.f / denom;
        for (int i = lane; i < deg; i += 32) w[(size_t)(off + i) * Hh + h] *= inv;
        if (lane == 0) wself[gw] = exs * inv;
    }
}

// block per node: gather-aggregate + bias + residual + LayerNorm1 (fused)
// writes m1 fp32 + bf16 hi/lo split
__global__ void __launch_bounds__(256) agg_ln1_kernel(
        const int* __restrict__ offs, const int* __restrict__ csrc,
        const float* __restrict__ w, const float* __restrict__ wself,
        const float* __restrict__ xp, const float* __restrict__ m,
        const float* __restrict__ bias,
        const float* __restrict__ gamma, const float* __restrict__ beta,
        float* __restrict__ out, bf16* __restrict__ ohi, bf16* __restrict__ olo) {
    int n = blockIdx.x;
    int t = threadIdx.x;
    int h = t >> 5, lane = t & 31;
    __shared__ int ssrc[128];
    __shared__ float sh[40];
    __shared__ int soff, sdeg;
    if (t == 0) { soff = offs[n]; sdeg = offs[n + 1] - offs[n]; }
    __syncthreads();
    int off = soff, deg = sdeg;

    float acc = wself[n * Hh + h] * xp[(size_t)n * Dd + h * Cc + lane];
    for (int c0 = 0; c0 < deg; c0 += 128) {
        int cn = min(128, deg - c0);
        __syncthreads();
        if (t < cn) ssrc[t] = csrc[off + c0 + t];
        __syncthreads();
        for (int i = 0; i < cn; ++i) {
            int s = ssrc[i];
            float ww = w[(size_t)(off + c0 + i) * Hh + h];
            acc += ww * xp[(size_t)s * Dd + h * Cc + lane];
        }
    }

    float r = acc + bias[t] + m[(size_t)n * Dd + t];
    float s = wred_sum(r);
    if (lane == 0) sh[h] = s;
    __syncthreads();
    if (t < 8) {
        float v = sh[t];
        #pragma unroll
        for (int o = 4; o; o >>= 1) v += __shfl_xor_sync(0xffu, v, o);
        if (t == 0) sh[32] = v;
    }
    __syncthreads();
    float mean = sh[32] * (1.0f / Dd);
    float dv = r - mean;
    float sq = wred_sum(dv * dv);
    if (lane == 0) sh[h] = sq;
    __syncthreads();
    if (t < 8) {
        float v = sh[t];
        #pragma unroll
        for (int o = 4; o; o >>= 1) v += __shfl_xor_sync(0xffu, v, o);
        if (t == 0) sh[33] = v;
    }
    __syncthreads();
    float var = sh[33] * (1.0f / Dd);
    size_t oidx = (size_t)n * Dd + t;
    float val = dv * rsqrtf(var + 1e-5f) * gamma[t] + beta[t];
    out[oidx] = val;
    bf16 hh, ll; split2(val, hh, ll);
    ohi[oidx] = hh; olo[oidx] = ll;
}

// LayerNorm over D=256 of (a + b); optional fp32 out + optional bf16 split out
__global__ void ln_kernel(const float* __restrict__ a, const float* __restrict__ b,
                          const float* __restrict__ gamma, const float* __restrict__ beta,
                          float* __restrict__ out, bf16* __restrict__ ohi, bf16* __restrict__ olo) {
    int n = blockIdx.x;
    int t = threadIdx.x;
    int h = t >> 5, lane = t & 31;
    size_t off = (size_t)n * Dd + t;
    float r = a[off] + b[off];
    __shared__ float sh[40];
    float s = wred_sum(r);
    if (lane == 0) sh[h] = s;
    __syncthreads();
    if (t < 8) {
        float v = sh[t];
        #pragma unroll
        for (int o = 4; o; o >>= 1) v += __shfl_xor_sync(0xffu, v, o);
        if (t == 0) sh[32] = v;
    }
    __syncthreads();
    float mean = sh[32] * (1.0f / Dd);
    float dv = r - mean;
    float sq = wred_sum(dv * dv);
    if (lane == 0) sh[h] = sq;
    __syncthreads();
    if (t < 8) {
        float v = sh[t];
        #pragma unroll
        for (int o = 4; o; o >>= 1) v += __shfl_xor_sync(0xffu, v, o);
        if (t == 0) sh[33] = v;
    }
    __syncthreads();
    float var = sh[33] * (1.0f / Dd);
    float val = dv * rsqrtf(var + 1e-5f) * gamma[t] + beta[t];
    out[off] = val;
    if (ohi) {
        bf16 hh, ll; split2(val, hh, ll);
        ohi[off] = hh; olo[off] = ll;
    }
}

// ---------------- tensor-core GEMM (pre-split bf16, 3-term, cp.async pipelined) ----
__device__ __forceinline__ void mma_bf16(float& d0, float& d1, float& d2, float& d3,
                                         unsigned a0, unsigned a1, unsigned a2, unsigned a3,
                                         unsigned b0, unsigned b1) {
    asm volatile("mma.sync.aligned.m16n8k16.row.col.f32.bf16.bf16.f32 "
                 "{%0,%1,%2,%3}, {%4,%5,%6,%7}, {%8,%9}, {%0,%1,%2,%3};\n"
                 : "+f"(d0), "+f"(d1), "+f"(d2), "+f"(d3)
                 : "r"(a0), "r"(a1), "r"(a2), "r"(a3), "r"(b0), "r"(b1));
}
__device__ __forceinline__ void cp16(unsigned dst, const void* src, int bytes) {
    asm volatile("cp.async.cg.shared.global [%0], [%1], 16, %2;\n"
                 :: "r"(dst), "l"(src), "r"(bytes));
}
__device__ __forceinline__ void cp_commit() { asm volatile("cp.async.commit_group;\n"); }
__device__ __forceinline__ void cp_wait1()  { asm volatile("cp.async.wait_group 1;\n"); }

#define GBM 128
#define GBN 128
#define GBK 32
#define GKP 40
#define GTILE (GBM*GKP)
#define GSMEM (2*4*GTILE*2)   // bytes: 2 stages x 4 arrays x 128x40 bf16 = 81920

// C[M,N] = A[M,K] @ B[K,N]; A,B pre-split bf16 (A row-major [M][K], B [N][K]).
// SPLIT_OUT: write bf16 hi/lo instead of fp32.
template<bool BIAS, bool RELU, bool SPLIT_OUT>
__global__ void __launch_bounds__(256) gemm_bf16(int M, int N, int K,
        const bf16* __restrict__ Ahi, const bf16* __restrict__ Alo,
        const bf16* __restrict__ Bhi, const bf16* __restrict__ Blo,
        const float* __restrict__ bias, float* __restrict__ C,
        bf16* __restrict__ Chi, bf16* __restrict__ Clo) {
    extern __shared__ __align__(16) bf16 sdyn[];
    int tid = threadIdx.x;
    int bm0 = blockIdx.y * GBM, bn0 = blockIdx.x * GBN;
    int w = tid >> 5, lane = tid & 31;
    int wm = w & 1, wn = w >> 1;           // 2 x 4 warp grid -> warp tile 64(M) x 32(N)
    int g = lane >> 2, tig = lane & 3;

    // cp.async mapping: 2 threads per row, each thread 16 contiguous elems (2x16B)
    int lr = tid >> 1;            // 0..127
    int lk = (tid & 1) * 16;      // 0 or 16

    float acc[4][4][4];
    #pragma unroll
    for (int i = 0; i < 4; ++i)
        #pragma unroll
        for (int j = 0; j < 4; ++j)
            #pragma unroll
            for (int q = 0; q < 4; ++q) acc[i][j][q] = 0.f;

    int arow = bm0 + lr;
    int abytes = (arow < M) ? 16 : 0;
    size_t aoffbase = (size_t)min(arow, M - 1) * K + lk;
    size_t boffbase = (size_t)(bn0 + lr) * K + lk;
    unsigned sA0 = (unsigned)__cvta_generic_to_shared(sdyn) + (unsigned)((lr * GKP + lk) * 2);

    auto load_stage = [&](int s, int k0) {
        unsigned base = sA0 + (unsigned)(s * 4 * GTILE * 2);
        const bf16* pa = Ahi + aoffbase + k0;
        cp16(base, pa, abytes);               cp16(base + 16, pa + 8, abytes);
        const bf16* pal = Alo + aoffbase + k0;
        unsigned d1 = base + GTILE * 2;
        cp16(d1, pal, abytes);                cp16(d1 + 16, pal + 8, abytes);
        const bf16* pb = Bhi + boffbase + k0;
        unsigned d2 = base + 2 * GTILE * 2;
        cp16(d2, pb, 16);                     cp16(d2 + 16, pb + 8, 16);
        const bf16* pbl = Blo + boffbase + k0;
        unsigned d3 = base + 3 * GTILE * 2;
        cp16(d3, pbl, 16);                    cp16(d3 + 16, pbl + 8, 16);
    };

    load_stage(0, 0);
    cp_commit();

    int s = 0;
    for (int k0 = 0; k0 < K; k0 += GBK, s ^= 1) {
        if (k0 + GBK < K) load_stage(s ^ 1, k0 + GBK);
        cp_commit();
        cp_wait1();
        __syncthreads();

        bf16* Ah = sdyn + (s * 4 + 0) * GTILE;
        bf16* Al = sdyn + (s * 4 + 1) * GTILE;
        bf16* Bh = sdyn + (s * 4 + 2) * GTILE;
        bf16* Bl = sdyn + (s * 4 + 3) * GTILE;

        #pragma unroll
        for (int kk = 0; kk < GBK; kk += 16) {
            unsigned afh[4][4], afl[4][4], bfh[4][2], bfl[4][2];
            int base = kk + 2 * tig;
            #pragma unroll
            for (int mt = 0; mt < 4; ++mt) {
                int r0 = wm * 64 + mt * 16 + g;
                afh[mt][0] = *reinterpret_cast<unsigned*>(&Ah[r0 * GKP + base]);
                afh[mt][1] = *reinterpret_cast<unsigned*>(&Ah[(r0 + 8) * GKP + base]);
                afh[mt][2] = *reinterpret_cast<unsigned*>(&Ah[r0 * GKP + base + 8]);
                afh[mt][3] = *reinterpret_cast<unsigned*>(&Ah[(r0 + 8) * GKP + base + 8]);
                afl[mt][0] = *reinterpret_cast<unsigned*>(&Al[r0 * GKP + base]);
                afl[mt][1] = *reinterpret_cast<unsigned*>(&Al[(r0 + 8) * GKP + base]);
                afl[mt][2] = *reinterpret_cast<unsigned*>(&Al[r0 * GKP + base + 8]);
                afl[mt][3] = *reinterpret_cast<unsigned*>(&Al[(r0 + 8) * GKP + base + 8]);
            }
            #pragma unroll
            for (int nt = 0; nt < 4; ++nt) {
                int c0 = wn * 32 + nt * 8 + g;
                bfh[nt][0] = *reinterpret_cast<unsigned*>(&Bh[c0 * GKP + base]);
                bfh[nt][1] = *reinterpret_cast<unsigned*>(&Bh[c0 * GKP + base + 8]);
                bfl[nt][0] = *reinterpret_cast<unsigned*>(&Bl[c0 * GKP + base]);
                bfl[nt][1] = *reinterpret_cast<unsigned*>(&Bl[c0 * GKP + base + 8]);
            }
            #pragma unroll
            for (int mt = 0; mt < 4; ++mt)
                #pragma unroll
                for (int nt = 0; nt < 4; ++nt) {
                    mma_bf16(acc[mt][nt][0], acc[mt][nt][1], acc[mt][nt][2], acc[mt][nt][3],
                             afh[mt][0], afh[mt][1], afh[mt][2], afh[mt][3],
                             bfh[nt][0], bfh[nt][1]);
                    mma_bf16(acc[mt][nt][0], acc[mt][nt][1], acc[mt][nt][2], acc[mt][nt][3],
                             afh[mt][0], afh[mt][1], afh[mt][2], afh[mt][3],
                             bfl[nt][0], bfl[nt][1]);
                    mma_bf16(acc[mt][nt][0], acc[mt][nt][1], acc[mt][nt][2], acc[mt][nt][3],
                             afl[mt][0], afl[mt][1], afl[mt][2], afl[mt][3],
                             bfh[nt][0], bfh[nt][1]);
                }
        }
        __syncthreads();
    }

    // epilogue
    #pragma unroll
    for (int mt = 0; mt < 4; ++mt) {
        #pragma unroll
        for (int half = 0; half < 2; ++half) {
            int row = bm0 + wm * 64 + mt * 16 + g + half * 8;
            if (row < M) {
                #pragma unroll
                for (int nt = 0; nt < 4; ++nt) {
                    int col = bn0 + wn * 32 + nt * 8 + 2 * tig;
                    float vx = acc[mt][nt][half * 2 + 0];
                    float vy = acc[mt][nt][half * 2 + 1];
                    if (BIAS) { vx += bias[col]; vy += bias[col + 1]; }
                    if (RELU) { vx = fmaxf(vx, 0.f); vy = fmaxf(vy, 0.f); }
                    if (SPLIT_OUT) {
                        bf16 hx, lx, hy, ly;
                        split2(vx, hx, lx); split2(vy, hy, ly);
                        *reinterpret_cast<bf162*>(Chi + (size_t)row * N + col) = bf162(hx, hy);
                        *reinterpret_cast<bf162*>(Clo + (size_t)row * N + col) = bf162(lx, ly);
                    } else {
                        float2 v; v.x = vx; v.y = vy;
                        *reinterpret_cast<float2*>(C + (size_t)row * N + col) = v;
                    }
                }
            }
        }
    }
}

// ---------------- orchestration ----------------
static inline void* symaddr(const void* sym) {
    void* p = nullptr;
    cudaGetSymbolAddress(&p, sym);
    return p;
}

extern "C" void kernel_launch(void* const* d_in, const int* in_sizes, int n_in,
                              void* d_out, int out_size) {
    const float* x        = (const float*)d_in[0];
    const void*  ei       = d_in[1];
    const float* edge_attr= (const float*)d_in[2];
    const float* W        = (const float*)d_in[3];
    const float* att_src  = (const float*)d_in[4];
    const float* att_dst  = (const float*)d_in[5];
    const float* att_edge = (const float*)d_in[6];
    const float* W_edge   = (const float*)d_in[7];
    const float* bias     = (const float*)d_in[8];
    const float* ffn_w1   = (const float*)d_in[9];
    const float* ffn_b1   = (const float*)d_in[10];
    const float* ffn_w2   = (const float*)d_in[11];
    const float* ffn_b2   = (const float*)d_in[12];
    const float* ln1_g    = (const float*)d_in[13];
    const float* ln1_b    = (const float*)d_in[14];
    const float* ln2_g    = (const float*)d_in[15];
    const float* ln2_b    = (const float*)d_in[16];
    float* out = (float*)d_out;

    float* pm     = (float*)symaddr(g_m);
    bf16*  pmhi   = (bf16*)symaddr(g_mhi);
    bf16*  pmlo   = (bf16*)symaddr(g_mlo);
    float* pxp    = (float*)symaddr(g_xp);
    float* pm1    = (float*)symaddr(g_m1);
    bf16*  pm1hi  = (bf16*)symaddr(g_m1hi);
    bf16*  pm1lo  = (bf16*)symaddr(g_m1lo);
    bf16*  phhi   = (bf16*)symaddr(g_hhi);
    bf16*  phlo   = (bf16*)symaddr(g_hlo);
    float* ph2    = (float*)symaddr(g_h2);
    float* pw     = (float*)symaddr(g_w);
    float* pwself = (float*)symaddr(g_wself);
    float* paedge = (float*)symaddr(g_aedge);
    float* pasrc  = (float*)symaddr(g_asrc);
    float* padst  = (float*)symaddr(g_adst);
    float* peasum = (float*)symaddr(g_easum);
    float* peamean= (float*)symaddr(g_eamean);
    float* pv     = (float*)symaddr(g_v);
    int*   psrc   = (int*)symaddr(g_src32);
    int*   pdst   = (int*)symaddr(g_dst32);
    int*   pdegi  = (int*)symaddr(g_degi);
    int*   poffs  = (int*)symaddr(g_offs);
    int*   pcur   = (int*)symaddr(g_cursor);
    int*   pcsrc  = (int*)symaddr(g_csrc);
    int*   pposof = (int*)symaddr(g_posof);
    bf16*  pWhi   = (bf16*)symaddr(g_Whi);
    bf16*  pWlo   = (bf16*)symaddr(g_Wlo);
    bf16*  pw1hi  = (bf16*)symaddr(g_w1hi);
    bf16*  pw1lo  = (bf16*)symaddr(g_w1lo);
    bf16*  pw2hi  = (bf16*)symaddr(g_w2hi);
    bf16*  pw2lo  = (bf16*)symaddr(g_w2lo);

    const int T = 256;
    auto blk = [](long long n, int t) { return (unsigned)((n + t - 1) / t); };

    // allow 80KB dynamic smem for the gemm template instantiations
    cudaFuncSetAttribute(gemm_bf16<false,false,false>,
                         cudaFuncAttributeMaxDynamicSharedMemorySize, GSMEM);
    cudaFuncSetAttribute(gemm_bf16<true,true,true>,
                         cudaFuncAttributeMaxDynamicSharedMemorySize, GSMEM);
    cudaFuncSetAttribute(gemm_bf16<true,false,false>,
                         cudaFuncAttributeMaxDynamicSharedMemorySize, GSMEM);

    // ---- one-time precompute ----
    zeroi_kernel<<<blk(Nn, T), T>>>(pdegi, Nn);
    zerof_kernel<<<blk((long long)Nn * EDd, T), T>>>(peasum, Nn * EDd);
    convert_idx_kernel<<<blk(Ee, T), T>>>(ei, psrc, pdst, pdegi);
    scan_kernel<<<1, 256>>>(pdegi, poffs, pcur);
    scatter_kernel<<<blk(Ee, T), T>>>(psrc, pdst, pcur, pcsrc, pposof);
    easum_kernel<<<blk((long long)Ee * EDd, T), T>>>(pdst, edge_attr, peasum);
    eamean_kernel<<<blk((long long)Nn * EDd, T), T>>>(peasum, pdegi, peamean);
    v_kernel<<<1, 128>>>(W_edge, att_edge, pv);
    aedge_kernel<<<blk((long long)(Ee + Nn), T), T>>>(edge_attr, peamean, pv, pposof, paedge);
    split_act_kernel<<<blk((long long)Nn * Dd, T), T>>>(x, pm, pmhi, pmlo, Nn * Dd);

    // weight pre-split (transposed bf16 hi/lo)
    splitT_kernel<<<blk((long long)Dd * Dd, T), T>>>(W, Dd, Dd, pWhi, pWlo);
    for (int i = 0; i < Ll; ++i) {
        splitT_kernel<<<blk((long long)Dd * D4, T), T>>>(
            ffn_w1 + (size_t)i * Dd * D4, Dd, D4,
            pw1hi + (size_t)i * Dd * D4, pw1lo + (size_t)i * Dd * D4);
        splitT_kernel<<<blk((long long)D4 * Dd, T), T>>>(
            ffn_w2 + (size_t)i * D4 * Dd, D4, Dd,
            pw2hi + (size_t)i * D4 * Dd, pw2lo + (size_t)i * D4 * Dd);
    }

    dim3 gProj(Dd / 128, (Nn + 127) / 128);
    dim3 gF1(D4 / 128, (Nn + 127) / 128);
    dim3 gF2(Dd / 128, (Nn + 127) / 128);
    unsigned gW = blk((long long)Nn * Hh * 32, T);

    for (int i = 0; i < Ll; ++i) {
        gemm_bf16<false, false, false><<<gProj, 256, GSMEM>>>(
            Nn, Dd, Dd, pmhi, pmlo, pWhi, pWlo, nullptr, pxp, nullptr, nullptr);
        asrc_adst_kernel<<<gW, T>>>(pxp, att_src, att_dst, pasrc, padst);
        attw_kernel<<<gW, T>>>(poffs, pcsrc, pasrc, padst, paedge, pw, pwself);
        agg_ln1_kernel<<<Nn, 256>>>(poffs, pcsrc, pw, pwself, pxp, pm, bias,
                                    ln1_g + i * Dd, ln1_b + i * Dd, pm1, pm1hi, pm1lo);
        gemm_bf16<true, true, true><<<gF1, 256, GSMEM>>>(
            Nn, D4, Dd, pm1hi, pm1lo,
            pw1hi + (size_t)i * Dd * D4, pw1lo + (size_t)i * Dd * D4,
            ffn_b1 + (size_t)i * D4, nullptr, phhi, phlo);
        gemm_bf16<true, false, false><<<gF2, 256, GSMEM>>>(
            Nn, Dd, D4, phhi, phlo,
            pw2hi + (size_t)i * D4 * Dd, pw2lo + (size_t)i * D4 * Dd,
            ffn_b2 + (size_t)i * Dd, ph2, nullptr, nullptr);
        if (i == Ll - 1) {
            ln_kernel<<<Nn, 256>>>(ph2, pm1, ln2_g + i * Dd, ln2_b + i * Dd,
                                   out, nullptr, nullptr);
        } else {
            ln_kernel<<<Nn, 256>>>(ph2, pm1, ln2_g + i * Dd, ln2_b + i * Dd,
                                   pm, pmhi, pmlo);
        }
    }
}

// round 8
// speedup vs baseline: 3.0063x; 1.2135x over previous
#include <cuda_runtime.h>
#include <cuda_bf16.h>
#include <cuda_fp16.h>

// Problem constants (fixed shapes per reference)
#define Nn 50000
#define Ee 800000
#define Dd 256
#define Hh 8
#define Cc 32
#define EDd 16
#define Ll 6
#define D4 (4*Dd)

typedef __half f16;

// ---------------- device scratch ----------------
__device__ float    g_m    [Nn*Dd];
__device__ f16      g_mhi  [Nn*Dd],  g_mlo  [Nn*Dd];
__device__ float    g_xp   [Nn*Dd];
__device__ float    g_m1   [Nn*Dd];
__device__ f16      g_m1hi [Nn*Dd],  g_m1lo [Nn*Dd];
__device__ f16      g_hhi  [Nn*D4],  g_hlo  [Nn*D4];
__device__ float    g_h2   [Nn*Dd];
__device__ float    g_w    [Ee*Hh];
__device__ float    g_wself[Nn*Hh];
__device__ float    g_aedge[(Ee+Nn)*Hh];
__device__ float    g_asrc [Nn*Hh];
__device__ float    g_adst [Nn*Hh];
__device__ float    g_easum[Nn*EDd];
__device__ float    g_eamean[Nn*EDd];
__device__ float    g_v    [EDd*Hh];
__device__ int      g_src32[Ee];
__device__ int      g_dst32[Ee];
__device__ int      g_degi [Nn];
__device__ int      g_offs [Nn+1];
__device__ int      g_cursor[Nn];
__device__ int      g_csrc [Ee];
__device__ int      g_posof[Ee];
// fp16 weights, transposed [N][K] (single term — B-side lo is dropped by design)
__device__ f16 g_Wh [Dd*Dd];
__device__ f16 g_w1h[Ll*Dd*D4];
__device__ f16 g_w2h[Ll*D4*Dd];

__device__ __forceinline__ float lrelu(float x) { return x > 0.f ? x : 0.2f * x; }
__device__ __forceinline__ int clampN(int v) { return v < 0 ? 0 : (v >= Nn ? Nn - 1 : v); }
__device__ __forceinline__ float wred_max(float v) {
    #pragma unroll
    for (int o = 16; o; o >>= 1) v = fmaxf(v, __shfl_xor_sync(0xffffffffu, v, o));
    return v;
}
__device__ __forceinline__ float wred_sum(float v) {
    #pragma unroll
    for (int o = 16; o; o >>= 1) v += __shfl_xor_sync(0xffffffffu, v, o);
    return v;
}
__device__ __forceinline__ void split2h(float x, f16& h, f16& l) {
    h = __float2half_rn(x);
    l = __float2half_rn(x - __half2float(h));
}

// ---------------- index conversion with on-device dtype detection ----------------
__global__ void convert_idx_kernel(const void* eiraw, int* src32, int* dst32, int* degi) {
    const long long* ei64 = (const long long*)eiraw;
    bool is64 = true;
    #pragma unroll
    for (int k = 0; k < 8; ++k) {
        unsigned long long v = (unsigned long long)ei64[k];
        if (v >= (unsigned long long)Nn) is64 = false;
    }
    int e = blockIdx.x * blockDim.x + threadIdx.x;
    if (e >= Ee) return;
    int s, d;
    if (is64) { s = (int)ei64[e]; d = (int)ei64[e + Ee]; }
    else      { const int* ei32 = (const int*)eiraw; s = ei32[e]; d = ei32[e + Ee]; }
    s = clampN(s); d = clampN(d);
    src32[e] = s;
    dst32[e] = d;
    atomicAdd(&degi[d], 1);
}

// ---------------- small utility kernels ----------------
__global__ void split_act_kernel(const float* __restrict__ src, float* __restrict__ dstf,
                                 f16* __restrict__ hi, f16* __restrict__ lo, int n) {
    int i = blockIdx.x * blockDim.x + threadIdx.x;
    if (i >= n) return;
    float v = src[i];
    if (dstf) dstf[i] = v;
    f16 h, l; split2h(v, h, l);
    hi[i] = h; lo[i] = l;
}
__global__ void zerof_kernel(float* __restrict__ p, int n) {
    int i = blockIdx.x * blockDim.x + threadIdx.x;
    if (i < n) p[i] = 0.f;
}
__global__ void zeroi_kernel(int* __restrict__ p, int n) {
    int i = blockIdx.x * blockDim.x + threadIdx.x;
    if (i < n) p[i] = 0;
}

// convert fp32 weight [K][N] into fp16 transposed [N][K]
__global__ void cvtT_kernel(const float* __restrict__ Wsrc, int K, int N,
                            f16* __restrict__ hi) {
    int idx = blockIdx.x * blockDim.x + threadIdx.x;
    if (idx >= K * N) return;
    int k = idx / N, n = idx - k * N;
    hi[(size_t)n * K + k] = __float2half_rn(Wsrc[idx]);
}

// single-block exclusive scan of degrees -> offsets + cursor copy
__global__ void scan_kernel(const int* __restrict__ degi, int* __restrict__ offs,
                            int* __restrict__ cursor) {
    __shared__ int part[256];
    int t = threadIdx.x;
    const int CH = (Nn + 255) / 256;
    int s = 0;
    for (int i = 0; i < CH; ++i) {
        int idx = t * CH + i;
        if (idx < Nn) s += degi[idx];
    }
    part[t] = s;
    __syncthreads();
    if (t == 0) {
        int acc = 0;
        for (int i = 0; i < 256; ++i) { int v = part[i]; part[i] = acc; acc += v; }
    }
    __syncthreads();
    int run = part[t];
    for (int i = 0; i < CH; ++i) {
        int idx = t * CH + i;
        if (idx < Nn) {
            offs[idx] = run;
            cursor[idx] = run;
            run += degi[idx];
        }
    }
    if (t == 0) offs[Nn] = Ee;
}

__global__ void scatter_kernel(const int* __restrict__ src, const int* __restrict__ dst,
                               int* __restrict__ cursor, int* __restrict__ csrc,
                               int* __restrict__ posof) {
    int e = blockIdx.x * blockDim.x + threadIdx.x;
    if (e >= Ee) return;
    int d = dst[e];
    int p = atomicAdd(&cursor[d], 1);
    csrc[p] = src[e];
    posof[e] = p;
}

__global__ void easum_kernel(const int* __restrict__ dst, const float* __restrict__ ea,
                             float* __restrict__ easum) {
    int idx = blockIdx.x * blockDim.x + threadIdx.x;
    if (idx >= Ee * EDd) return;
    int e = idx >> 4, j = idx & 15;
    atomicAdd(&easum[dst[e] * EDd + j], ea[idx]);
}
__global__ void eamean_kernel(const float* __restrict__ easum, const int* __restrict__ degi,
                              float* __restrict__ eamean) {
    int idx = blockIdx.x * blockDim.x + threadIdx.x;
    if (idx >= Nn * EDd) return;
    int n = idx >> 4;
    eamean[idx] = easum[idx] / fmaxf((float)degi[n], 1.0f);
}
__global__ void v_kernel(const float* __restrict__ W_edge, const float* __restrict__ att_edge,
                         float* __restrict__ v) {
    int t = threadIdx.x;
    if (t >= EDd * Hh) return;
    int d = t >> 3, h = t & 7;
    float s = 0.f;
    #pragma unroll
    for (int c = 0; c < Cc; ++c) s += W_edge[d * Dd + h * Cc + c] * att_edge[h * Cc + c];
    v[d * Hh + h] = s;
}
__global__ void aedge_kernel(const float* __restrict__ ea, const float* __restrict__ eamean,
                             const float* __restrict__ v, const int* __restrict__ posof,
                             float* __restrict__ aedge) {
    int e = blockIdx.x * blockDim.x + threadIdx.x;
    if (e >= Ee + Nn) return;
    const float* p = (e < Ee) ? (ea + (size_t)e * EDd) : (eamean + (size_t)(e - Ee) * EDd);
    float r[EDd];
    #pragma unroll
    for (int j = 0; j < EDd; ++j) r[j] = p[j];
    size_t row = (e < Ee) ? (size_t)posof[e] : (size_t)e;
    #pragma unroll
    for (int h = 0; h < Hh; ++h) {
        float s = 0.f;
        #pragma unroll
        for (int j = 0; j < EDd; ++j) s += r[j] * v[j * Hh + h];
        aedge[row * Hh + h] = s;
    }
}

// warp per (node, head): a_src and a_dst dot products
__global__ void asrc_adst_kernel(const float* __restrict__ xp,
                                 const float* __restrict__ att_src,
                                 const float* __restrict__ att_dst,
                                 float* __restrict__ asrc, float* __restrict__ adst) {
    int gw = (blockIdx.x * blockDim.x + threadIdx.x) >> 5;
    int lane = threadIdx.x & 31;
    if (gw >= Nn * Hh) return;
    int n = gw >> 3, h = gw & 7;
    float v = xp[(size_t)n * Dd + h * Cc + lane];
    float s = wred_sum(v * att_src[h * Cc + lane]);
    float d = wred_sum(v * att_dst[h * Cc + lane]);
    if (lane == 0) { asrc[gw] = s; adst[gw] = d; }
}

// warp per (node, head): softmax over incoming edges (CSR)
__global__ void attw_kernel(const int* __restrict__ offs, const int* __restrict__ csrc,
                            const float* __restrict__ asrc, const float* __restrict__ adst,
                            const float* __restrict__ aedge,
                            float* __restrict__ w, float* __restrict__ wself) {
    int gw = (blockIdx.x * blockDim.x + threadIdx.x) >> 5;
    int lane = threadIdx.x & 31;
    if (gw >= Nn * Hh) return;
    int n = gw >> 3, h = gw & 7;
    int off = offs[n];
    int deg = offs[n + 1] - off;
    float adstn = adst[gw];
    float al_self = lrelu(asrc[gw] + adstn + aedge[(size_t)(Ee + n) * Hh + h]);

    if (deg <= 32) {
        float al = -3.4e38f;
        if (lane < deg) {
            int s = csrc[off + lane];
            al = lrelu(asrc[s * Hh + h] + adstn + aedge[(size_t)(off + lane) * Hh + h]);
        }
        float M = fmaxf(al_self, wred_max(al));
        float ex = (lane < deg) ? expf(al - M) : 0.f;
        float exs = expf(al_self - M);
        float denom = exs + wred_sum(ex);
        if (lane < deg) w[(size_t)(off + lane) * Hh + h] = ex / denom;
        if (lane == 0) wself[gw] = exs / denom;
    } else {
        float M = al_self;
        for (int i = lane; i < deg; i += 32) {
            int s = csrc[off + i];
            float al = lrelu(asrc[s * Hh + h] + adstn + aedge[(size_t)(off + i) * Hh + h]);
            w[(size_t)(off + i) * Hh + h] = al;
            M = fmaxf(M, al);
        }
        M = wred_max(M);
        float sum = 0.f;
        for (int i = lane; i < deg; i += 32) {
            float ex = expf(w[(size_t)(off + i) * Hh + h] - M);
            w[(size_t)(off + i) * Hh + h] = ex;
            sum += ex;
        }
        float exs = expf(al_self - M);
        float denom = exs + wred_sum(sum);
        float inv = 1.f / denom;
        for (int i = lane; i < deg; i += 32) w[(size_t)(off + i) * Hh + h] *= inv;
        if (lane == 0) wself[gw] = exs * inv;
    }
}

// block per node: gather-aggregate + bias + residual + LayerNorm1 (fused)
__global__ void __launch_bounds__(256) agg_ln1_kernel(
        const int* __restrict__ offs, const int* __restrict__ csrc,
        const float* __restrict__ w, const float* __restrict__ wself,
        const float* __restrict__ xp, const float* __restrict__ m,
        const float* __restrict__ bias,
        const float* __restrict__ gamma, const float* __restrict__ beta,
        float* __restrict__ out, f16* __restrict__ ohi, f16* __restrict__ olo) {
    int n = blockIdx.x;
    int t = threadIdx.x;
    int h = t >> 5, lane = t & 31;
    __shared__ int ssrc[128];
    __shared__ float sh[40];
    __shared__ int soff, sdeg;
    if (t == 0) { soff = offs[n]; sdeg = offs[n + 1] - offs[n]; }
    __syncthreads();
    int off = soff, deg = sdeg;

    float acc = wself[n * Hh + h] * xp[(size_t)n * Dd + h * Cc + lane];
    for (int c0 = 0; c0 < deg; c0 += 128) {
        int cn = min(128, deg - c0);
        __syncthreads();
        if (t < cn) ssrc[t] = csrc[off + c0 + t];
        __syncthreads();
        for (int i = 0; i < cn; ++i) {
            int s = ssrc[i];
            float ww = w[(size_t)(off + c0 + i) * Hh + h];
            acc += ww * xp[(size_t)s * Dd + h * Cc + lane];
        }
    }

    float r = acc + bias[t] + m[(size_t)n * Dd + t];
    float s = wred_sum(r);
    if (lane == 0) sh[h] = s;
    __syncthreads();
    if (t < 8) {
        float v = sh[t];
        #pragma unroll
        for (int o = 4; o; o >>= 1) v += __shfl_xor_sync(0xffu, v, o);
        if (t == 0) sh[32] = v;
    }
    __syncthreads();
    float mean = sh[32] * (1.0f / Dd);
    float dv = r - mean;
    float sq = wred_sum(dv * dv);
    if (lane == 0) sh[h] = sq;
    __syncthreads();
    if (t < 8) {
        float v = sh[t];
        #pragma unroll
        for (int o = 4; o; o >>= 1) v += __shfl_xor_sync(0xffu, v, o);
        if (t == 0) sh[33] = v;
    }
    __syncthreads();
    float var = sh[33] * (1.0f / Dd);
    size_t oidx = (size_t)n * Dd + t;
    float val = dv * rsqrtf(var + 1e-5f) * gamma[t] + beta[t];
    out[oidx] = val;
    f16 hh, ll; split2h(val, hh, ll);
    ohi[oidx] = hh; olo[oidx] = ll;
}

// LayerNorm over D=256 of (a + b); optional fp16 split out
__global__ void ln_kernel(const float* __restrict__ a, const float* __restrict__ b,
                          const float* __restrict__ gamma, const float* __restrict__ beta,
                          float* __restrict__ out, f16* __restrict__ ohi, f16* __restrict__ olo) {
    int n = blockIdx.x;
    int t = threadIdx.x;
    int h = t >> 5, lane = t & 31;
    size_t off = (size_t)n * Dd + t;
    float r = a[off] + b[off];
    __shared__ float sh[40];
    float s = wred_sum(r);
    if (lane == 0) sh[h] = s;
    __syncthreads();
    if (t < 8) {
        float v = sh[t];
        #pragma unroll
        for (int o = 4; o; o >>= 1) v += __shfl_xor_sync(0xffu, v, o);
        if (t == 0) sh[32] = v;
    }
    __syncthreads();
    float mean = sh[32] * (1.0f / Dd);
    float dv = r - mean;
    float sq = wred_sum(dv * dv);
    if (lane == 0) sh[h] = sq;
    __syncthreads();
    if (t < 8) {
        float v = sh[t];
        #pragma unroll
        for (int o = 4; o; o >>= 1) v += __shfl_xor_sync(0xffu, v, o);
        if (t == 0) sh[33] = v;
    }
    __syncthreads();
    float var = sh[33] * (1.0f / Dd);
    float val = dv * rsqrtf(var + 1e-5f) * gamma[t] + beta[t];
    out[off] = val;
    if (ohi) {
        f16 hh, ll; split2h(val, hh, ll);
        ohi[off] = hh; olo[off] = ll;
    }
}

// ---------------- tensor-core GEMM (fp16 2-term: (Ah+Al)@Bh, cp.async pipelined) ----
__device__ __forceinline__ void mma_f16(float& d0, float& d1, float& d2, float& d3,
                                        unsigned a0, unsigned a1, unsigned a2, unsigned a3,
                                        unsigned b0, unsigned b1) {
    asm volatile("mma.sync.aligned.m16n8k16.row.col.f32.f16.f16.f32 "
                 "{%0,%1,%2,%3}, {%4,%5,%6,%7}, {%8,%9}, {%0,%1,%2,%3};\n"
                 : "+f"(d0), "+f"(d1), "+f"(d2), "+f"(d3)
                 : "r"(a0), "r"(a1), "r"(a2), "r"(a3), "r"(b0), "r"(b1));
}
__device__ __forceinline__ void cp16(unsigned dst, const void* src, int bytes) {
    asm volatile("cp.async.cg.shared.global [%0], [%1], 16, %2;\n"
                 :: "r"(dst), "l"(src), "r"(bytes));
}
__device__ __forceinline__ void cp_commit() { asm volatile("cp.async.commit_group;\n"); }
__device__ __forceinline__ void cp_wait1()  { asm volatile("cp.async.wait_group 1;\n"); }

#define GBM 128
#define GBN 128
#define GBK 32
#define GKP 40
#define GTILE (GBM*GKP)
#define GSMEM (2*3*GTILE*2)   // bytes: 2 stages x 3 arrays x 128x40 f16 = 61440

// C[M,N] = A[M,K] @ B[K,N]; A fp16 hi/lo [M][K], B fp16 [N][K].
template<bool BIAS, bool RELU, bool SPLIT_OUT>
__global__ void __launch_bounds__(256) gemm_f16(int M, int N, int K,
        const f16* __restrict__ Ahi, const f16* __restrict__ Alo,
        const f16* __restrict__ Bh16,
        const float* __restrict__ bias, float* __restrict__ C,
        f16* __restrict__ Chi, f16* __restrict__ Clo) {
    extern __shared__ __align__(16) f16 sdyn[];
    int tid = threadIdx.x;
    int bm0 = blockIdx.y * GBM, bn0 = blockIdx.x * GBN;
    int w = tid >> 5, lane = tid & 31;
    int wm = w & 1, wn = w >> 1;           // 2 x 4 warp grid -> warp tile 64(M) x 32(N)
    int g = lane >> 2, tig = lane & 3;

    // cp.async mapping: 2 threads per row, each thread 16 contiguous elems (2x16B)
    int lr = tid >> 1;            // 0..127
    int lk = (tid & 1) * 16;      // 0 or 16

    float acc[4][4][4];
    #pragma unroll
    for (int i = 0; i < 4; ++i)
        #pragma unroll
        for (int j = 0; j < 4; ++j)
            #pragma unroll
            for (int q = 0; q < 4; ++q) acc[i][j][q] = 0.f;

    int arow = bm0 + lr;
    int abytes = (arow < M) ? 16 : 0;
    size_t aoffbase = (size_t)min(arow, M - 1) * K + lk;
    size_t boffbase = (size_t)(bn0 + lr) * K + lk;
    unsigned sA0 = (unsigned)__cvta_generic_to_shared(sdyn) + (unsigned)((lr * GKP + lk) * 2);

    auto load_stage = [&](int s, int k0) {
        unsigned base = sA0 + (unsigned)(s * 3 * GTILE * 2);
        const f16* pa = Ahi + aoffbase + k0;
        cp16(base, pa, abytes);               cp16(base + 16, pa + 8, abytes);
        const f16* pal = Alo + aoffbase + k0;
        unsigned d1 = base + GTILE * 2;
        cp16(d1, pal, abytes);                cp16(d1 + 16, pal + 8, abytes);
        const f16* pb = Bh16 + boffbase + k0;
        unsigned d2 = base + 2 * GTILE * 2;
        cp16(d2, pb, 16);                     cp16(d2 + 16, pb + 8, 16);
    };

    load_stage(0, 0);
    cp_commit();

    int s = 0;
    for (int k0 = 0; k0 < K; k0 += GBK, s ^= 1) {
        if (k0 + GBK < K) load_stage(s ^ 1, k0 + GBK);
        cp_commit();
        cp_wait1();
        __syncthreads();

        f16* Ah = sdyn + (s * 3 + 0) * GTILE;
        f16* Al = sdyn + (s * 3 + 1) * GTILE;
        f16* Bh = sdyn + (s * 3 + 2) * GTILE;

        #pragma unroll
        for (int kk = 0; kk < GBK; kk += 16) {
            unsigned afh[4][4], afl[4][4], bfh[4][2];
            int base = kk + 2 * tig;
            #pragma unroll
            for (int mt = 0; mt < 4; ++mt) {
                int r0 = wm * 64 + mt * 16 + g;
                afh[mt][0] = *reinterpret_cast<unsigned*>(&Ah[r0 * GKP + base]);
                afh[mt][1] = *reinterpret_cast<unsigned*>(&Ah[(r0 + 8) * GKP + base]);
                afh[mt][2] = *reinterpret_cast<unsigned*>(&Ah[r0 * GKP + base + 8]);
                afh[mt][3] = *reinterpret_cast<unsigned*>(&Ah[(r0 + 8) * GKP + base + 8]);
                afl[mt][0] = *reinterpret_cast<unsigned*>(&Al[r0 * GKP + base]);
                afl[mt][1] = *reinterpret_cast<unsigned*>(&Al[(r0 + 8) * GKP + base]);
                afl[mt][2] = *reinterpret_cast<unsigned*>(&Al[r0 * GKP + base + 8]);
                afl[mt][3] = *reinterpret_cast<unsigned*>(&Al[(r0 + 8) * GKP + base + 8]);
            }
            #pragma unroll
            for (int nt = 0; nt < 4; ++nt) {
                int c0 = wn * 32 + nt * 8 + g;
                bfh[nt][0] = *reinterpret_cast<unsigned*>(&Bh[c0 * GKP + base]);
                bfh[nt][1] = *reinterpret_cast<unsigned*>(&Bh[c0 * GKP + base + 8]);
            }
            #pragma unroll
            for (int mt = 0; mt < 4; ++mt)
                #pragma unroll
                for (int nt = 0; nt < 4; ++nt) {
                    mma_f16(acc[mt][nt][0], acc[mt][nt][1], acc[mt][nt][2], acc[mt][nt][3],
                            afh[mt][0], afh[mt][1], afh[mt][2], afh[mt][3],
                            bfh[nt][0], bfh[nt][1]);
                    mma_f16(acc[mt][nt][0], acc[mt][nt][1], acc[mt][nt][2], acc[mt][nt][3],
                            afl[mt][0], afl[mt][1], afl[mt][2], afl[mt][3],
                            bfh[nt][0], bfh[nt][1]);
                }
        }
        __syncthreads();
    }

    // epilogue
    #pragma unroll
    for (int mt = 0; mt < 4; ++mt) {
        #pragma unroll
        for (int half = 0; half < 2; ++half) {
            int row = bm0 + wm * 64 + mt * 16 + g + half * 8;
            if (row < M) {
                #pragma unroll
                for (int nt = 0; nt < 4; ++nt) {
                    int col = bn0 + wn * 32 + nt * 8 + 2 * tig;
                    float vx = acc[mt][nt][half * 2 + 0];
                    float vy = acc[mt][nt][half * 2 + 1];
                    if (BIAS) { vx += bias[col]; vy += bias[col + 1]; }
                    if (RELU) { vx = fmaxf(vx, 0.f); vy = fmaxf(vy, 0.f); }
                    if (SPLIT_OUT) {
                        f16 hx, lx, hy, ly;
                        split2h(vx, hx, lx); split2h(vy, hy, ly);
                        *reinterpret_cast<__half2*>(Chi + (size_t)row * N + col) =
                            __halves2half2(hx, hy);
                        *reinterpret_cast<__half2*>(Clo + (size_t)row * N + col) =
                            __halves2half2(lx, ly);
                    } else {
                        float2 v; v.x = vx; v.y = vy;
                        *reinterpret_cast<float2*>(C + (size_t)row * N + col) = v;
                    }
                }
            }
        }
    }
}

// ---------------- orchestration ----------------
static inline void* symaddr(const void* sym) {
    void* p = nullptr;
    cudaGetSymbolAddress(&p, sym);
    return p;
}

extern "C" void kernel_launch(void* const* d_in, const int* in_sizes, int n_in,
                              void* d_out, int out_size) {
    const float* x        = (const float*)d_in[0];
    const void*  ei       = d_in[1];
    const float* edge_attr= (const float*)d_in[2];
    const float* W        = (const float*)d_in[3];
    const float* att_src  = (const float*)d_in[4];
    const float* att_dst  = (const float*)d_in[5];
    const float* att_edge = (const float*)d_in[6];
    const float* W_edge   = (const float*)d_in[7];
    const float* bias     = (const float*)d_in[8];
    const float* ffn_w1   = (const float*)d_in[9];
    const float* ffn_b1   = (const float*)d_in[10];
    const float* ffn_w2   = (const float*)d_in[11];
    const float* ffn_b2   = (const float*)d_in[12];
    const float* ln1_g    = (const float*)d_in[13];
    const float* ln1_b    = (const float*)d_in[14];
    const float* ln2_g    = (const float*)d_in[15];
    const float* ln2_b    = (const float*)d_in[16];
    float* out = (float*)d_out;

    float* pm     = (float*)symaddr(g_m);
    f16*   pmhi   = (f16*)symaddr(g_mhi);
    f16*   pmlo   = (f16*)symaddr(g_mlo);
    float* pxp    = (float*)symaddr(g_xp);
    float* pm1    = (float*)symaddr(g_m1);
    f16*   pm1hi  = (f16*)symaddr(g_m1hi);
    f16*   pm1lo  = (f16*)symaddr(g_m1lo);
    f16*   phhi   = (f16*)symaddr(g_hhi);
    f16*   phlo   = (f16*)symaddr(g_hlo);
    float* ph2    = (float*)symaddr(g_h2);
    float* pw     = (float*)symaddr(g_w);
    float* pwself = (float*)symaddr(g_wself);
    float* paedge = (float*)symaddr(g_aedge);
    float* pasrc  = (float*)symaddr(g_asrc);
    float* padst  = (float*)symaddr(g_adst);
    float* peasum = (float*)symaddr(g_easum);
    float* peamean= (float*)symaddr(g_eamean);
    float* pv     = (float*)symaddr(g_v);
    int*   psrc   = (int*)symaddr(g_src32);
    int*   pdst   = (int*)symaddr(g_dst32);
    int*   pdegi  = (int*)symaddr(g_degi);
    int*   poffs  = (int*)symaddr(g_offs);
    int*   pcur   = (int*)symaddr(g_cursor);
    int*   pcsrc  = (int*)symaddr(g_csrc);
    int*   pposof = (int*)symaddr(g_posof);
    f16*   pWh    = (f16*)symaddr(g_Wh);
    f16*   pw1h   = (f16*)symaddr(g_w1h);
    f16*   pw2h   = (f16*)symaddr(g_w2h);

    const int T = 256;
    auto blk = [](long long n, int t) { return (unsigned)((n + t - 1) / t); };

    cudaFuncSetAttribute(gemm_f16<false,false,false>,
                         cudaFuncAttributeMaxDynamicSharedMemorySize, GSMEM);
    cudaFuncSetAttribute(gemm_f16<true,true,true>,
                         cudaFuncAttributeMaxDynamicSharedMemorySize, GSMEM);
    cudaFuncSetAttribute(gemm_f16<true,false,false>,
                         cudaFuncAttributeMaxDynamicSharedMemorySize, GSMEM);

    // ---- one-time precompute ----
    zeroi_kernel<<<blk(Nn, T), T>>>(pdegi, Nn);
    zerof_kernel<<<blk((long long)Nn * EDd, T), T>>>(peasum, Nn * EDd);
    convert_idx_kernel<<<blk(Ee, T), T>>>(ei, psrc, pdst, pdegi);
    scan_kernel<<<1, 256>>>(pdegi, poffs, pcur);
    scatter_kernel<<<blk(Ee, T), T>>>(psrc, pdst, pcur, pcsrc, pposof);
    easum_kernel<<<blk((long long)Ee * EDd, T), T>>>(pdst, edge_attr, peasum);
    eamean_kernel<<<blk((long long)Nn * EDd, T), T>>>(peasum, pdegi, peamean);
    v_kernel<<<1, 128>>>(W_edge, att_edge, pv);
    aedge_kernel<<<blk((long long)(Ee + Nn), T), T>>>(edge_attr, peamean, pv, pposof, paedge);
    split_act_kernel<<<blk((long long)Nn * Dd, T), T>>>(x, pm, pmhi, pmlo, Nn * Dd);

    cvtT_kernel<<<blk((long long)Dd * Dd, T), T>>>(W, Dd, Dd, pWh);
    for (int i = 0; i < Ll; ++i) {
        cvtT_kernel<<<blk((long long)Dd * D4, T), T>>>(
            ffn_w1 + (size_t)i * Dd * D4, Dd, D4, pw1h + (size_t)i * Dd * D4);
        cvtT_kernel<<<blk((long long)D4 * Dd, T), T>>>(
            ffn_w2 + (size_t)i * D4 * Dd, D4, Dd, pw2h + (size_t)i * D4 * Dd);
    }

    dim3 gProj(Dd / 128, (Nn + 127) / 128);
    dim3 gF1(D4 / 128, (Nn + 127) / 128);
    dim3 gF2(Dd / 128, (Nn + 127) / 128);
    unsigned gW = blk((long long)Nn * Hh * 32, T);

    for (int i = 0; i < Ll; ++i) {
        gemm_f16<false, false, false><<<gProj, 256, GSMEM>>>(
            Nn, Dd, Dd, pmhi, pmlo, pWh, nullptr, pxp, nullptr, nullptr);
        asrc_adst_kernel<<<gW, T>>>(pxp, att_src, att_dst, pasrc, padst);
        attw_kernel<<<gW, T>>>(poffs, pcsrc, pasrc, padst, paedge, pw, pwself);
        agg_ln1_kernel<<<Nn, 256>>>(poffs, pcsrc, pw, pwself, pxp, pm, bias,
                                    ln1_g + i * Dd, ln1_b + i * Dd, pm1, pm1hi, pm1lo);
        gemm_f16<true, true, true><<<gF1, 256, GSMEM>>>(
            Nn, D4, Dd, pm1hi, pm1lo, pw1h + (size_t)i * Dd * D4,
            ffn_b1 + (size_t)i * D4, nullptr, phhi, phlo);
        gemm_f16<true, false, false><<<gF2, 256, GSMEM>>>(
            Nn, Dd, D4, phhi, phlo, pw2h + (size_t)i * D4 * Dd,
            ffn_b2 + (size_t)i * Dd, ph2, nullptr, nullptr);
        if (i == Ll - 1) {
            ln_kernel<<<Nn, 256>>>(ph2, pm1, ln2_g + i * Dd, ln2_b + i * Dd,
                                   out, nullptr, nullptr);
        } else {
            ln_kernel<<<Nn, 256>>>(ph2, pm1, ln2_g + i * Dd, ln2_b + i * Dd,
                                   pm, pmhi, pmlo);
        }
    }
}

// round 9
// speedup vs baseline: 3.1324x; 1.0420x over previous
#include <cuda_runtime.h>
#include <cuda_bf16.h>
#include <cuda_fp16.h>

// Problem constants (fixed shapes per reference)
#define Nn 50000
#define Ee 800000
#define Dd 256
#define Hh 8
#define Cc 32
#define EDd 16
#define Ll 6
#define D4 (4*Dd)
#define EPN (Ee+Nn)

typedef __half f16;

// ---------------- device scratch ----------------
__device__ float    g_m    [Nn*Dd];
__device__ f16      g_mhi  [Nn*Dd],  g_mlo  [Nn*Dd];
__device__ float    g_xp   [Nn*Dd];
__device__ float    g_m1   [Nn*Dd];
__device__ f16      g_m1hi [Nn*Dd],  g_m1lo [Nn*Dd];
__device__ f16      g_hhi  [Nn*D4],  g_hlo  [Nn*D4];
__device__ float    g_h2   [Nn*Dd];
__device__ float    g_w    [Hh*(size_t)Ee];   // plane layout [h][pos]
__device__ float    g_wself[Nn*Hh];
__device__ float    g_aedge[Hh*(size_t)EPN];  // plane layout [h][pos]; self at Ee+n
__device__ float    g_asrc [Nn*Hh];
__device__ float    g_adst [Nn*Hh];
__device__ float    g_easum[Nn*EDd];
__device__ float    g_eamean[Nn*EDd];
__device__ float    g_v    [EDd*Hh];
__device__ int      g_src32[Ee];
__device__ int      g_dst32[Ee];
__device__ int      g_degi [Nn];
__device__ int      g_offs [Nn+1];
__device__ int      g_cursor[Nn];
__device__ int      g_csrc [Ee];
__device__ int      g_posof[Ee];
// fp16 weights, transposed [N][K]
__device__ f16 g_Wh [Dd*Dd];
__device__ f16 g_w1h[Ll*Dd*D4];
__device__ f16 g_w2h[Ll*D4*Dd];

__device__ __forceinline__ float lrelu(float x) { return x > 0.f ? x : 0.2f * x; }
__device__ __forceinline__ int clampN(int v) { return v < 0 ? 0 : (v >= Nn ? Nn - 1 : v); }
__device__ __forceinline__ float wred_max(float v) {
    #pragma unroll
    for (int o = 16; o; o >>= 1) v = fmaxf(v, __shfl_xor_sync(0xffffffffu, v, o));
    return v;
}
__device__ __forceinline__ float wred_sum(float v) {
    #pragma unroll
    for (int o = 16; o; o >>= 1) v += __shfl_xor_sync(0xffffffffu, v, o);
    return v;
}
__device__ __forceinline__ void split2h(float x, f16& h, f16& l) {
    h = __float2half_rn(x);
    l = __float2half_rn(x - __half2float(h));
}

// ---------------- index conversion with on-device dtype detection ----------------
__global__ void convert_idx_kernel(const void* eiraw, int* src32, int* dst32, int* degi) {
    const long long* ei64 = (const long long*)eiraw;
    bool is64 = true;
    #pragma unroll
    for (int k = 0; k < 8; ++k) {
        unsigned long long v = (unsigned long long)ei64[k];
        if (v >= (unsigned long long)Nn) is64 = false;
    }
    int e = blockIdx.x * blockDim.x + threadIdx.x;
    if (e >= Ee) return;
    int s, d;
    if (is64) { s = (int)ei64[e]; d = (int)ei64[e + Ee]; }
    else      { const int* ei32 = (const int*)eiraw; s = ei32[e]; d = ei32[e + Ee]; }
    s = clampN(s); d = clampN(d);
    src32[e] = s;
    dst32[e] = d;
    atomicAdd(&degi[d], 1);
}

// ---------------- small utility kernels ----------------
__global__ void split_act_kernel(const float* __restrict__ src, float* __restrict__ dstf,
                                 f16* __restrict__ hi, f16* __restrict__ lo, int n) {
    int i = blockIdx.x * blockDim.x + threadIdx.x;
    if (i >= n) return;
    float v = src[i];
    if (dstf) dstf[i] = v;
    f16 h, l; split2h(v, h, l);
    hi[i] = h; lo[i] = l;
}
__global__ void zerof_kernel(float* __restrict__ p, int n) {
    int i = blockIdx.x * blockDim.x + threadIdx.x;
    if (i < n) p[i] = 0.f;
}
__global__ void zeroi_kernel(int* __restrict__ p, int n) {
    int i = blockIdx.x * blockDim.x + threadIdx.x;
    if (i < n) p[i] = 0;
}

// convert fp32 weight [K][N] into fp16 transposed [N][K]
__global__ void cvtT_kernel(const float* __restrict__ Wsrc, int K, int N,
                            f16* __restrict__ hi) {
    int idx = blockIdx.x * blockDim.x + threadIdx.x;
    if (idx >= K * N) return;
    int k = idx / N, n = idx - k * N;
    hi[(size_t)n * K + k] = __float2half_rn(Wsrc[idx]);
}

// single-block exclusive scan of degrees -> offsets + cursor copy
__global__ void scan_kernel(const int* __restrict__ degi, int* __restrict__ offs,
                            int* __restrict__ cursor) {
    __shared__ int part[256];
    int t = threadIdx.x;
    const int CH = (Nn + 255) / 256;
    int s = 0;
    for (int i = 0; i < CH; ++i) {
        int idx = t * CH + i;
        if (idx < Nn) s += degi[idx];
    }
    part[t] = s;
    __syncthreads();
    if (t == 0) {
        int acc = 0;
        for (int i = 0; i < 256; ++i) { int v = part[i]; part[i] = acc; acc += v; }
    }
    __syncthreads();
    int run = part[t];
    for (int i = 0; i < CH; ++i) {
        int idx = t * CH + i;
        if (idx < Nn) {
            offs[idx] = run;
            cursor[idx] = run;
            run += degi[idx];
        }
    }
    if (t == 0) offs[Nn] = Ee;
}

__global__ void scatter_kernel(const int* __restrict__ src, const int* __restrict__ dst,
                               int* __restrict__ cursor, int* __restrict__ csrc,
                               int* __restrict__ posof) {
    int e = blockIdx.x * blockDim.x + threadIdx.x;
    if (e >= Ee) return;
    int d = dst[e];
    int p = atomicAdd(&cursor[d], 1);
    csrc[p] = src[e];
    posof[e] = p;
}

__global__ void easum_kernel(const int* __restrict__ dst, const float* __restrict__ ea,
                             float* __restrict__ easum) {
    int idx = blockIdx.x * blockDim.x + threadIdx.x;
    if (idx >= Ee * EDd) return;
    int e = idx >> 4, j = idx & 15;
    atomicAdd(&easum[dst[e] * EDd + j], ea[idx]);
}
__global__ void eamean_kernel(const float* __restrict__ easum, const int* __restrict__ degi,
                              float* __restrict__ eamean) {
    int idx = blockIdx.x * blockDim.x + threadIdx.x;
    if (idx >= Nn * EDd) return;
    int n = idx >> 4;
    eamean[idx] = easum[idx] / fmaxf((float)degi[n], 1.0f);
}
__global__ void v_kernel(const float* __restrict__ W_edge, const float* __restrict__ att_edge,
                         float* __restrict__ v) {
    int t = threadIdx.x;
    if (t >= EDd * Hh) return;
    int d = t >> 3, h = t & 7;
    float s = 0.f;
    #pragma unroll
    for (int c = 0; c < Cc; ++c) s += W_edge[d * Dd + h * Cc + c] * att_edge[h * Cc + c];
    v[d * Hh + h] = s;
}
// a_edge in CSR order, PLANE layout: aedge[h*EPN + pos]
__global__ void aedge_kernel(const float* __restrict__ ea, const float* __restrict__ eamean,
                             const float* __restrict__ v, const int* __restrict__ posof,
                             float* __restrict__ aedge) {
    int e = blockIdx.x * blockDim.x + threadIdx.x;
    if (e >= EPN) return;
    const float* p = (e < Ee) ? (ea + (size_t)e * EDd) : (eamean + (size_t)(e - Ee) * EDd);
    float r[EDd];
    #pragma unroll
    for (int j = 0; j < EDd; ++j) r[j] = p[j];
    size_t row = (e < Ee) ? (size_t)posof[e] : (size_t)e;
    #pragma unroll
    for (int h = 0; h < Hh; ++h) {
        float s = 0.f;
        #pragma unroll
        for (int j = 0; j < EDd; ++j) s += r[j] * v[j * Hh + h];
        aedge[(size_t)h * EPN + row] = s;
    }
}

// warp per (node, head): a_src and a_dst dot products
__global__ void asrc_adst_kernel(const float* __restrict__ xp,
                                 const float* __restrict__ att_src,
                                 const float* __restrict__ att_dst,
                                 float* __restrict__ asrc, float* __restrict__ adst) {
    int gw = (blockIdx.x * blockDim.x + threadIdx.x) >> 5;
    int lane = threadIdx.x & 31;
    if (gw >= Nn * Hh) return;
    int n = gw >> 3, h = gw & 7;
    float v = xp[(size_t)n * Dd + h * Cc + lane];
    float s = wred_sum(v * att_src[h * Cc + lane]);
    float d = wred_sum(v * att_dst[h * Cc + lane]);
    if (lane == 0) { asrc[gw] = s; adst[gw] = d; }
}

// warp per (node, head): softmax over incoming edges (CSR); plane layouts
__global__ void attw_kernel(const int* __restrict__ offs, const int* __restrict__ csrc,
                            const float* __restrict__ asrc, const float* __restrict__ adst,
                            const float* __restrict__ aedge,
                            float* __restrict__ w, float* __restrict__ wself) {
    int gw = (blockIdx.x * blockDim.x + threadIdx.x) >> 5;
    int lane = threadIdx.x & 31;
    if (gw >= Nn * Hh) return;
    int n = gw >> 3, h = gw & 7;
    int off = offs[n];
    int deg = offs[n + 1] - off;
    const float* aeP = aedge + (size_t)h * EPN;
    float* wP = w + (size_t)h * Ee;
    float adstn = adst[gw];
    float al_self = lrelu(asrc[gw] + adstn + aeP[Ee + n]);

    if (deg <= 32) {
        float al = -3.4e38f;
        if (lane < deg) {
            int s = csrc[off + lane];
            al = lrelu(asrc[s * Hh + h] + adstn + aeP[off + lane]);
        }
        float M = fmaxf(al_self, wred_max(al));
        float ex = (lane < deg) ? expf(al - M) : 0.f;
        float exs = expf(al_self - M);
        float denom = exs + wred_sum(ex);
        if (lane < deg) wP[off + lane] = ex / denom;
        if (lane == 0) wself[gw] = exs / denom;
    } else {
        float M = al_self;
        for (int i = lane; i < deg; i += 32) {
            int s = csrc[off + i];
            float al = lrelu(asrc[s * Hh + h] + adstn + aeP[off + i]);
            wP[off + i] = al;
            M = fmaxf(M, al);
        }
        M = wred_max(M);
        float sum = 0.f;
        for (int i = lane; i < deg; i += 32) {
            float ex = expf(wP[off + i] - M);
            wP[off + i] = ex;
            sum += ex;
        }
        float exs = expf(al_self - M);
        float denom = exs + wred_sum(sum);
        float inv = 1.f / denom;
        for (int i = lane; i < deg; i += 32) wP[off + i] *= inv;
        if (lane == 0) wself[gw] = exs * inv;
    }
}

// block per node: gather-aggregate + bias + residual + LayerNorm1 (fused), unroll-4
__global__ void __launch_bounds__(256) agg_ln1_kernel(
        const int* __restrict__ offs, const int* __restrict__ csrc,
        const float* __restrict__ w, const float* __restrict__ wself,
        const float* __restrict__ xp, const float* __restrict__ m,
        const float* __restrict__ bias,
        const float* __restrict__ gamma, const float* __restrict__ beta,
        float* __restrict__ out, f16* __restrict__ ohi, f16* __restrict__ olo) {
    int n = blockIdx.x;
    int t = threadIdx.x;
    int h = t >> 5, lane = t & 31;
    __shared__ int ssrc[128];
    __shared__ float sh[40];
    __shared__ int soff, sdeg;
    if (t == 0) { soff = offs[n]; sdeg = offs[n + 1] - offs[n]; }
    __syncthreads();
    int off = soff, deg = sdeg;
    const float* wP = w + (size_t)h * Ee;
    int xcol = h * Cc + lane;

    float acc = wself[n * Hh + h] * xp[(size_t)n * Dd + xcol];
    for (int c0 = 0; c0 < deg; c0 += 128) {
        int cn = min(128, deg - c0);
        __syncthreads();
        if (t < cn) ssrc[t] = csrc[off + c0 + t];
        __syncthreads();
        const float* wB = wP + off + c0;
        int i = 0;
        for (; i + 4 <= cn; i += 4) {
            int s0 = ssrc[i], s1 = ssrc[i + 1], s2 = ssrc[i + 2], s3 = ssrc[i + 3];
            float w0 = wB[i], w1 = wB[i + 1], w2 = wB[i + 2], w3 = wB[i + 3];
            float x0 = xp[(size_t)s0 * Dd + xcol];
            float x1 = xp[(size_t)s1 * Dd + xcol];
            float x2 = xp[(size_t)s2 * Dd + xcol];
            float x3 = xp[(size_t)s3 * Dd + xcol];
            acc += w0 * x0; acc += w1 * x1; acc += w2 * x2; acc += w3 * x3;
        }
        for (; i < cn; ++i) {
            int s = ssrc[i];
            acc += wB[i] * xp[(size_t)s * Dd + xcol];
        }
    }

    float r = acc + bias[t] + m[(size_t)n * Dd + t];
    float s = wred_sum(r);
    if (lane == 0) sh[h] = s;
    __syncthreads();
    if (t < 8) {
        float v = sh[t];
        #pragma unroll
        for (int o = 4; o; o >>= 1) v += __shfl_xor_sync(0xffu, v, o);
        if (t == 0) sh[32] = v;
    }
    __syncthreads();
    float mean = sh[32] * (1.0f / Dd);
    float dv = r - mean;
    float sq = wred_sum(dv * dv);
    if (lane == 0) sh[h] = sq;
    __syncthreads();
    if (t < 8) {
        float v = sh[t];
        #pragma unroll
        for (int o = 4; o; o >>= 1) v += __shfl_xor_sync(0xffu, v, o);
        if (t == 0) sh[33] = v;
    }
    __syncthreads();
    float var = sh[33] * (1.0f / Dd);
    size_t oidx = (size_t)n * Dd + t;
    float val = dv * rsqrtf(var + 1e-5f) * gamma[t] + beta[t];
    out[oidx] = val;
    f16 hh, ll; split2h(val, hh, ll);
    ohi[oidx] = hh; olo[oidx] = ll;
}

// LayerNorm over D=256 of (a + b); optional fp16 split out
__global__ void ln_kernel(const float* __restrict__ a, const float* __restrict__ b,
                          const float* __restrict__ gamma, const float* __restrict__ beta,
                          float* __restrict__ out, f16* __restrict__ ohi, f16* __restrict__ olo) {
    int n = blockIdx.x;
    int t = threadIdx.x;
    int h = t >> 5, lane = t & 31;
    size_t off = (size_t)n * Dd + t;
    float r = a[off] + b[off];
    __shared__ float sh[40];
    float s = wred_sum(r);
    if (lane == 0) sh[h] = s;
    __syncthreads();
    if (t < 8) {
        float v = sh[t];
        #pragma unroll
        for (int o = 4; o; o >>= 1) v += __shfl_xor_sync(0xffu, v, o);
        if (t == 0) sh[32] = v;
    }
    __syncthreads();
    float mean = sh[32] * (1.0f / Dd);
    float dv = r - mean;
    float sq = wred_sum(dv * dv);
    if (lane == 0) sh[h] = sq;
    __syncthreads();
    if (t < 8) {
        float v = sh[t];
        #pragma unroll
        for (int o = 4; o; o >>= 1) v += __shfl_xor_sync(0xffu, v, o);
        if (t == 0) sh[33] = v;
    }
    __syncthreads();
    float var = sh[33] * (1.0f / Dd);
    float val = dv * rsqrtf(var + 1e-5f) * gamma[t] + beta[t];
    out[off] = val;
    if (ohi) {
        f16 hh, ll; split2h(val, hh, ll);
        ohi[off] = hh; olo[off] = ll;
    }
}

// ---------------- tensor-core GEMM (fp16 2-term: (Ah+Al)@Bh, cp.async pipelined) ----
__device__ __forceinline__ void mma_f16(float& d0, float& d1, float& d2, float& d3,
                                        unsigned a0, unsigned a1, unsigned a2, unsigned a3,
                                        unsigned b0, unsigned b1) {
    asm volatile("mma.sync.aligned.m16n8k16.row.col.f32.f16.f16.f32 "
                 "{%0,%1,%2,%3}, {%4,%5,%6,%7}, {%8,%9}, {%0,%1,%2,%3};\n"
                 : "+f"(d0), "+f"(d1), "+f"(d2), "+f"(d3)
                 : "r"(a0), "r"(a1), "r"(a2), "r"(a3), "r"(b0), "r"(b1));
}
__device__ __forceinline__ void cp16(unsigned dst, const void* src, int bytes) {
    asm volatile("cp.async.cg.shared.global [%0], [%1], 16, %2;\n"
                 :: "r"(dst), "l"(src), "r"(bytes));
}
__device__ __forceinline__ void cp_commit() { asm volatile("cp.async.commit_group;\n"); }
__device__ __forceinline__ void cp_wait1()  { asm volatile("cp.async.wait_group 1;\n"); }

#define GBM 128
#define GBN 128
#define GBK 32
#define GKP 40
#define GTILE (GBM*GKP)
#define GSMEM (2*3*GTILE*2)   // bytes: 2 stages x 3 arrays x 128x40 f16 = 61440

// C[M,N] = A[M,K] @ B[K,N]; A fp16 hi/lo [M][K], B fp16 [N][K].
template<bool BIAS, bool RELU, bool SPLIT_OUT>
__global__ void __launch_bounds__(256) gemm_f16(int M, int N, int K,
        const f16* __restrict__ Ahi, const f16* __restrict__ Alo,
        const f16* __restrict__ Bh16,
        const float* __restrict__ bias, float* __restrict__ C,
        f16* __restrict__ Chi, f16* __restrict__ Clo) {
    extern __shared__ __align__(16) f16 sdyn[];
    int tid = threadIdx.x;
    int bm0 = blockIdx.y * GBM, bn0 = blockIdx.x * GBN;
    int w = tid >> 5, lane = tid & 31;
    int wm = w & 1, wn = w >> 1;           // 2 x 4 warp grid -> warp tile 64(M) x 32(N)
    int g = lane >> 2, tig = lane & 3;

    int lr = tid >> 1;            // 0..127
    int lk = (tid & 1) * 16;      // 0 or 16

    float acc[4][4][4];
    #pragma unroll
    for (int i = 0; i < 4; ++i)
        #pragma unroll
        for (int j = 0; j < 4; ++j)
            #pragma unroll
            for (int q = 0; q < 4; ++q) acc[i][j][q] = 0.f;

    int arow = bm0 + lr;
    int abytes = (arow < M) ? 16 : 0;
    size_t aoffbase = (size_t)min(arow, M - 1) * K + lk;
    size_t boffbase = (size_t)(bn0 + lr) * K + lk;
    unsigned sA0 = (unsigned)__cvta_generic_to_shared(sdyn) + (unsigned)((lr * GKP + lk) * 2);

    auto load_stage = [&](int s, int k0) {
        unsigned base = sA0 + (unsigned)(s * 3 * GTILE * 2);
        const f16* pa = Ahi + aoffbase + k0;
        cp16(base, pa, abytes);               cp16(base + 16, pa + 8, abytes);
        const f16* pal = Alo + aoffbase + k0;
        unsigned d1 = base + GTILE * 2;
        cp16(d1, pal, abytes);                cp16(d1 + 16, pal + 8, abytes);
        const f16* pb = Bh16 + boffbase + k0;
        unsigned d2 = base + 2 * GTILE * 2;
        cp16(d2, pb, 16);                     cp16(d2 + 16, pb + 8, 16);
    };

    load_stage(0, 0);
    cp_commit();

    int s = 0;
    for (int k0 = 0; k0 < K; k0 += GBK, s ^= 1) {
        if (k0 + GBK < K) load_stage(s ^ 1, k0 + GBK);
        cp_commit();
        cp_wait1();
        __syncthreads();

        f16* Ah = sdyn + (s * 3 + 0) * GTILE;
        f16* Al = sdyn + (s * 3 + 1) * GTILE;
        f16* Bh = sdyn + (s * 3 + 2) * GTILE;

        #pragma unroll
        for (int kk = 0; kk < GBK; kk += 16) {
            unsigned afh[4][4], afl[4][4], bfh[4][2];
            int base = kk + 2 * tig;
            #pragma unroll
            for (int mt = 0; mt < 4; ++mt) {
                int r0 = wm * 64 + mt * 16 + g;
                afh[mt][0] = *reinterpret_cast<unsigned*>(&Ah[r0 * GKP + base]);
                afh[mt][1] = *reinterpret_cast<unsigned*>(&Ah[(r0 + 8) * GKP + base]);
                afh[mt][2] = *reinterpret_cast<unsigned*>(&Ah[r0 * GKP + base + 8]);
                afh[mt][3] = *reinterpret_cast<unsigned*>(&Ah[(r0 + 8) * GKP + base + 8]);
                afl[mt][0] = *reinterpret_cast<unsigned*>(&Al[r0 * GKP + base]);
                afl[mt][1] = *reinterpret_cast<unsigned*>(&Al[(r0 + 8) * GKP + base]);
                afl[mt][2] = *reinterpret_cast<unsigned*>(&Al[r0 * GKP + base + 8]);
                afl[mt][3] = *reinterpret_cast<unsigned*>(&Al[(r0 + 8) * GKP + base + 8]);
            }
            #pragma unroll
            for (int nt = 0; nt < 4; ++nt) {
                int c0 = wn * 32 + nt * 8 + g;
                bfh[nt][0] = *reinterpret_cast<unsigned*>(&Bh[c0 * GKP + base]);
                bfh[nt][1] = *reinterpret_cast<unsigned*>(&Bh[c0 * GKP + base + 8]);
            }
            #pragma unroll
            for (int mt = 0; mt < 4; ++mt)
                #pragma unroll
                for (int nt = 0; nt < 4; ++nt) {
                    mma_f16(acc[mt][nt][0], acc[mt][nt][1], acc[mt][nt][2], acc[mt][nt][3],
                            afh[mt][0], afh[mt][1], afh[mt][2], afh[mt][3],
                            bfh[nt][0], bfh[nt][1]);
                    mma_f16(acc[mt][nt][0], acc[mt][nt][1], acc[mt][nt][2], acc[mt][nt][3],
                            afl[mt][0], afl[mt][1], afl[mt][2], afl[mt][3],
                            bfh[nt][0], bfh[nt][1]);
                }
        }
        __syncthreads();
    }

    // epilogue
    #pragma unroll
    for (int mt = 0; mt < 4; ++mt) {
        #pragma unroll
        for (int half = 0; half < 2; ++half) {
            int row = bm0 + wm * 64 + mt * 16 + g + half * 8;
            if (row < M) {
                #pragma unroll
                for (int nt = 0; nt < 4; ++nt) {
                    int col = bn0 + wn * 32 + nt * 8 + 2 * tig;
                    float vx = acc[mt][nt][half * 2 + 0];
                    float vy = acc[mt][nt][half * 2 + 1];
                    if (BIAS) { vx += bias[col]; vy += bias[col + 1]; }
                    if (RELU) { vx = fmaxf(vx, 0.f); vy = fmaxf(vy, 0.f); }
                    if (SPLIT_OUT) {
                        f16 hx, lx, hy, ly;
                        split2h(vx, hx, lx); split2h(vy, hy, ly);
                        *reinterpret_cast<__half2*>(Chi + (size_t)row * N + col) =
                            __halves2half2(hx, hy);
                        *reinterpret_cast<__half2*>(Clo + (size_t)row * N + col) =
                            __halves2half2(lx, ly);
                    } else {
                        float2 v; v.x = vx; v.y = vy;
                        *reinterpret_cast<float2*>(C + (size_t)row * N + col) = v;
                    }
                }
            }
        }
    }
}

// ---------------- orchestration ----------------
static inline void* symaddr(const void* sym) {
    void* p = nullptr;
    cudaGetSymbolAddress(&p, sym);
    return p;
}

extern "C" void kernel_launch(void* const* d_in, const int* in_sizes, int n_in,
                              void* d_out, int out_size) {
    const float* x        = (const float*)d_in[0];
    const void*  ei       = d_in[1];
    const float* edge_attr= (const float*)d_in[2];
    const float* W        = (const float*)d_in[3];
    const float* att_src  = (const float*)d_in[4];
    const float* att_dst  = (const float*)d_in[5];
    const float* att_edge = (const float*)d_in[6];
    const float* W_edge   = (const float*)d_in[7];
    const float* bias     = (const float*)d_in[8];
    const float* ffn_w1   = (const float*)d_in[9];
    const float* ffn_b1   = (const float*)d_in[10];
    const float* ffn_w2   = (const float*)d_in[11];
    const float* ffn_b2   = (const float*)d_in[12];
    const float* ln1_g    = (const float*)d_in[13];
    const float* ln1_b    = (const float*)d_in[14];
    const float* ln2_g    = (const float*)d_in[15];
    const float* ln2_b    = (const float*)d_in[16];
    float* out = (float*)d_out;

    float* pm     = (float*)symaddr(g_m);
    f16*   pmhi   = (f16*)symaddr(g_mhi);
    f16*   pmlo   = (f16*)symaddr(g_mlo);
    float* pxp    = (float*)symaddr(g_xp);
    float* pm1    = (float*)symaddr(g_m1);
    f16*   pm1hi  = (f16*)symaddr(g_m1hi);
    f16*   pm1lo  = (f16*)symaddr(g_m1lo);
    f16*   phhi   = (f16*)symaddr(g_hhi);
    f16*   phlo   = (f16*)symaddr(g_hlo);
    float* ph2    = (float*)symaddr(g_h2);
    float* pw     = (float*)symaddr(g_w);
    float* pwself = (float*)symaddr(g_wself);
    float* paedge = (float*)symaddr(g_aedge);
    float* pasrc  = (float*)symaddr(g_asrc);
    float* padst  = (float*)symaddr(g_adst);
    float* peasum = (float*)symaddr(g_easum);
    float* peamean= (float*)symaddr(g_eamean);
    float* pv     = (float*)symaddr(g_v);
    int*   psrc   = (int*)symaddr(g_src32);
    int*   pdst   = (int*)symaddr(g_dst32);
    int*   pdegi  = (int*)symaddr(g_degi);
    int*   poffs  = (int*)symaddr(g_offs);
    int*   pcur   = (int*)symaddr(g_cursor);
    int*   pcsrc  = (int*)symaddr(g_csrc);
    int*   pposof = (int*)symaddr(g_posof);
    f16*   pWh    = (f16*)symaddr(g_Wh);
    f16*   pw1h   = (f16*)symaddr(g_w1h);
    f16*   pw2h   = (f16*)symaddr(g_w2h);

    const int T = 256;
    auto blk = [](long long n, int t) { return (unsigned)((n + t - 1) / t); };

    cudaFuncSetAttribute(gemm_f16<false,false,false>,
                         cudaFuncAttributeMaxDynamicSharedMemorySize, GSMEM);
    cudaFuncSetAttribute(gemm_f16<true,true,true>,
                         cudaFuncAttributeMaxDynamicSharedMemorySize, GSMEM);
    cudaFuncSetAttribute(gemm_f16<true,false,false>,
                         cudaFuncAttributeMaxDynamicSharedMemorySize, GSMEM);

    // ---- one-time precompute ----
    zeroi_kernel<<<blk(Nn, T), T>>>(pdegi, Nn);
    zerof_kernel<<<blk((long long)Nn * EDd, T), T>>>(peasum, Nn * EDd);
    convert_idx_kernel<<<blk(Ee, T), T>>>(ei, psrc, pdst, pdegi);
    scan_kernel<<<1, 256>>>(pdegi, poffs, pcur);
    scatter_kernel<<<blk(Ee, T), T>>>(psrc, pdst, pcur, pcsrc, pposof);
    easum_kernel<<<blk((long long)Ee * EDd, T), T>>>(pdst, edge_attr, peasum);
    eamean_kernel<<<blk((long long)Nn * EDd, T), T>>>(peasum, pdegi, peamean);
    v_kernel<<<1, 128>>>(W_edge, att_edge, pv);
    aedge_kernel<<<blk((long long)EPN, T), T>>>(edge_attr, peamean, pv, pposof, paedge);
    split_act_kernel<<<blk((long long)Nn * Dd, T), T>>>(x, pm, pmhi, pmlo, Nn * Dd);

    cvtT_kernel<<<blk((long long)Dd * Dd, T), T>>>(W, Dd, Dd, pWh);
    for (int i = 0; i < Ll; ++i) {
        cvtT_kernel<<<blk((long long)Dd * D4, T), T>>>(
            ffn_w1 + (size_t)i * Dd * D4, Dd, D4, pw1h + (size_t)i * Dd * D4);
        cvtT_kernel<<<blk((long long)D4 * Dd, T), T>>>(
            ffn_w2 + (size_t)i * D4 * Dd, D4, Dd, pw2h + (size_t)i * D4 * Dd);
    }

    dim3 gProj(Dd / 128, (Nn + 127) / 128);
    dim3 gF1(D4 / 128, (Nn + 127) / 128);
    dim3 gF2(Dd / 128, (Nn + 127) / 128);
    unsigned gW = blk((long long)Nn * Hh * 32, T);

    for (int i = 0; i < Ll; ++i) {
        gemm_f16<false, false, false><<<gProj, 256, GSMEM>>>(
            Nn, Dd, Dd, pmhi, pmlo, pWh, nullptr, pxp, nullptr, nullptr);
        asrc_adst_kernel<<<gW, T>>>(pxp, att_src, att_dst, pasrc, padst);
        attw_kernel<<<gW, T>>>(poffs, pcsrc, pasrc, padst, paedge, pw, pwself);
        agg_ln1_kernel<<<Nn, 256>>>(poffs, pcsrc, pw, pwself, pxp, pm, bias,
                                    ln1_g + i * Dd, ln1_b + i * Dd, pm1, pm1hi, pm1lo);
        gemm_f16<true, true, true><<<gF1, 256, GSMEM>>>(
            Nn, D4, Dd, pm1hi, pm1lo, pw1h + (size_t)i * Dd * D4,
            ffn_b1 + (size_t)i * D4, nullptr, phhi, phlo);
        gemm_f16<true, false, false><<<gF2, 256, GSMEM>>>(
            Nn, Dd, D4, phhi, phlo, pw2h + (size_t)i * D4 * Dd,
            ffn_b2 + (size_t)i * Dd, ph2, nullptr, nullptr);
        if (i == Ll - 1) {
            ln_kernel<<<Nn, 256>>>(ph2, pm1, ln2_g + i * Dd, ln2_b + i * Dd,
                                   out, nullptr, nullptr);
        } else {
            ln_kernel<<<Nn, 256>>>(ph2, pm1, ln2_g + i * Dd, ln2_b + i * Dd,
                                   pm, pmhi, pmlo);
        }
    }
}

// round 10
// speedup vs baseline: 3.3828x; 1.0799x over previous
#include <cuda_runtime.h>
#include <cuda_bf16.h>
#include <cuda_fp16.h>

// Problem constants (fixed shapes per reference)
#define Nn 50000
#define Ee 800000
#define Dd 256
#define Hh 8
#define Cc 32
#define EDd 16
#define Ll 6
#define D4 (4*Dd)
#define EPN (Ee+Nn)
#define SCB 256
#define SCNB ((Nn+SCB-1)/SCB)

typedef __half f16;

// ---------------- device scratch ----------------
__device__ float    g_m    [Nn*Dd];
__device__ f16      g_mhi  [Nn*Dd],  g_mlo  [Nn*Dd];
__device__ float    g_xp   [Nn*Dd];
__device__ float    g_m1   [Nn*Dd];
__device__ f16      g_m1hi [Nn*Dd],  g_m1lo [Nn*Dd];
__device__ f16      g_hhi  [Nn*D4],  g_hlo  [Nn*D4];
__device__ float    g_h2   [Nn*Dd];
__device__ float    g_w    [Hh*(size_t)Ee];   // scratch for deg>32 softmax only
__device__ float    g_aedge[Hh*(size_t)EPN];  // plane layout [h][pos]; self at Ee+n
__device__ float    g_asrc [Nn*Hh];
__device__ float    g_adst [Nn*Hh];
__device__ float    g_easum[Nn*EDd];
__device__ float    g_eamean[Nn*EDd];
__device__ float    g_v    [EDd*Hh];
__device__ int      g_src32[Ee];
__device__ int      g_dst32[Ee];
__device__ int      g_degi [Nn];
__device__ int      g_offs [Nn+1];
__device__ int      g_cursor[Nn];
__device__ int      g_csrc [Ee];
__device__ int      g_posof[Ee];
__device__ int      g_bsum [SCNB];
__device__ int      g_boff [SCNB];
// fp16 weights, transposed [N][K]
__device__ f16 g_Wh [Dd*Dd];
__device__ f16 g_w1h[Ll*Dd*D4];
__device__ f16 g_w2h[Ll*D4*Dd];

__device__ __forceinline__ float lrelu(float x) { return x > 0.f ? x : 0.2f * x; }
__device__ __forceinline__ int clampN(int v) { return v < 0 ? 0 : (v >= Nn ? Nn - 1 : v); }
__device__ __forceinline__ float wred_max(float v) {
    #pragma unroll
    for (int o = 16; o; o >>= 1) v = fmaxf(v, __shfl_xor_sync(0xffffffffu, v, o));
    return v;
}
__device__ __forceinline__ float wred_sum(float v) {
    #pragma unroll
    for (int o = 16; o; o >>= 1) v += __shfl_xor_sync(0xffffffffu, v, o);
    return v;
}
__device__ __forceinline__ void split2h(float x, f16& h, f16& l) {
    h = __float2half_rn(x);
    l = __float2half_rn(x - __half2float(h));
}

// ---------------- index conversion with on-device dtype detection ----------------
__global__ void convert_idx_kernel(const void* eiraw, int* src32, int* dst32, int* degi) {
    const long long* ei64 = (const long long*)eiraw;
    bool is64 = true;
    #pragma unroll
    for (int k = 0; k < 8; ++k) {
        unsigned long long v = (unsigned long long)ei64[k];
        if (v >= (unsigned long long)Nn) is64 = false;
    }
    int e = blockIdx.x * blockDim.x + threadIdx.x;
    if (e >= Ee) return;
    int s, d;
    if (is64) { s = (int)ei64[e]; d = (int)ei64[e + Ee]; }
    else      { const int* ei32 = (const int*)eiraw; s = ei32[e]; d = ei32[e + Ee]; }
    s = clampN(s); d = clampN(d);
    src32[e] = s;
    dst32[e] = d;
    atomicAdd(&degi[d], 1);
}

// ---------------- small utility kernels ----------------
__global__ void split_act_kernel(const float* __restrict__ src, float* __restrict__ dstf,
                                 f16* __restrict__ hi, f16* __restrict__ lo, int n) {
    int i = blockIdx.x * blockDim.x + threadIdx.x;
    if (i >= n) return;
    float v = src[i];
    if (dstf) dstf[i] = v;
    f16 h, l; split2h(v, h, l);
    hi[i] = h; lo[i] = l;
}
__global__ void zerof_kernel(float* __restrict__ p, int n) {
    int i = blockIdx.x * blockDim.x + threadIdx.x;
    if (i < n) p[i] = 0.f;
}
__global__ void zeroi_kernel(int* __restrict__ p, int n) {
    int i = blockIdx.x * blockDim.x + threadIdx.x;
    if (i < n) p[i] = 0;
}

// convert fp32 weight [K][N] into fp16 transposed [N][K]
__global__ void cvtT_kernel(const float* __restrict__ Wsrc, int K, int N,
                            f16* __restrict__ hi) {
    int idx = blockIdx.x * blockDim.x + threadIdx.x;
    if (idx >= K * N) return;
    int k = idx / N, n = idx - k * N;
    hi[(size_t)n * K + k] = __float2half_rn(Wsrc[idx]);
}

// ---------------- parallel scan (3 kernels) ----------------
__global__ void scan1_kernel(const int* __restrict__ degi, int* __restrict__ offs,
                             int* __restrict__ bsum) {
    __shared__ int sm[SCB];
    int b = blockIdx.x, t = threadIdx.x;
    int idx = b * SCB + t;
    int v = (idx < Nn) ? degi[idx] : 0;
    sm[t] = v;
    __syncthreads();
    // Hillis-Steele inclusive scan
    #pragma unroll
    for (int o = 1; o < SCB; o <<= 1) {
        int add = (t >= o) ? sm[t - o] : 0;
        __syncthreads();
        sm[t] += add;
        __syncthreads();
    }
    if (idx < Nn) offs[idx] = sm[t] - v;     // block-local exclusive
    if (t == SCB - 1) bsum[b] = sm[t];
}
__global__ void scan2_kernel(const int* __restrict__ bsum, int* __restrict__ boff) {
    __shared__ int sm[SCB];
    int t = threadIdx.x;
    int v = (t < SCNB) ? bsum[t] : 0;
    sm[t] = v;
    __syncthreads();
    #pragma unroll
    for (int o = 1; o < SCB; o <<= 1) {
        int add = (t >= o) ? sm[t - o] : 0;
        __syncthreads();
        sm[t] += add;
        __syncthreads();
    }
    if (t < SCNB) boff[t] = sm[t] - v;
}
__global__ void scan3_kernel(int* __restrict__ offs, int* __restrict__ cursor,
                             const int* __restrict__ boff) {
    int b = blockIdx.x, t = threadIdx.x;
    int idx = b * SCB + t;
    if (idx < Nn) {
        int o = offs[idx] + boff[b];
        offs[idx] = o;
        cursor[idx] = o;
    }
    if (idx == 0) offs[Nn] = Ee;
}

__global__ void scatter_kernel(const int* __restrict__ src, const int* __restrict__ dst,
                               int* __restrict__ cursor, int* __restrict__ csrc,
                               int* __restrict__ posof) {
    int e = blockIdx.x * blockDim.x + threadIdx.x;
    if (e >= Ee) return;
    int d = dst[e];
    int p = atomicAdd(&cursor[d], 1);
    csrc[p] = src[e];
    posof[e] = p;
}

__global__ void easum_kernel(const int* __restrict__ dst, const float* __restrict__ ea,
                             float* __restrict__ easum) {
    int idx = blockIdx.x * blockDim.x + threadIdx.x;
    if (idx >= Ee * EDd) return;
    int e = idx >> 4, j = idx & 15;
    atomicAdd(&easum[dst[e] * EDd + j], ea[idx]);
}
__global__ void eamean_kernel(const float* __restrict__ easum, const int* __restrict__ degi,
                              float* __restrict__ eamean) {
    int idx = blockIdx.x * blockDim.x + threadIdx.x;
    if (idx >= Nn * EDd) return;
    int n = idx >> 4;
    eamean[idx] = easum[idx] / fmaxf((float)degi[n], 1.0f);
}
__global__ void v_kernel(const float* __restrict__ W_edge, const float* __restrict__ att_edge,
                         float* __restrict__ v) {
    int t = threadIdx.x;
    if (t >= EDd * Hh) return;
    int d = t >> 3, h = t & 7;
    float s = 0.f;
    #pragma unroll
    for (int c = 0; c < Cc; ++c) s += W_edge[d * Dd + h * Cc + c] * att_edge[h * Cc + c];
    v[d * Hh + h] = s;
}
// a_edge in CSR order, PLANE layout: aedge[h*EPN + pos]
__global__ void aedge_kernel(const float* __restrict__ ea, const float* __restrict__ eamean,
                             const float* __restrict__ v, const int* __restrict__ posof,
                             float* __restrict__ aedge) {
    int e = blockIdx.x * blockDim.x + threadIdx.x;
    if (e >= EPN) return;
    const float* p = (e < Ee) ? (ea + (size_t)e * EDd) : (eamean + (size_t)(e - Ee) * EDd);
    float r[EDd];
    #pragma unroll
    for (int j = 0; j < EDd; ++j) r[j] = p[j];
    size_t row = (e < Ee) ? (size_t)posof[e] : (size_t)e;
    #pragma unroll
    for (int h = 0; h < Hh; ++h) {
        float s = 0.f;
        #pragma unroll
        for (int j = 0; j < EDd; ++j) s += r[j] * v[j * Hh + h];
        aedge[(size_t)h * EPN + row] = s;
    }
}

// warp per (node, head): a_src and a_dst dot products
__global__ void asrc_adst_kernel(const float* __restrict__ xp,
                                 const float* __restrict__ att_src,
                                 const float* __restrict__ att_dst,
                                 float* __restrict__ asrc, float* __restrict__ adst) {
    int gw = (blockIdx.x * blockDim.x + threadIdx.x) >> 5;
    int lane = threadIdx.x & 31;
    if (gw >= Nn * Hh) return;
    int n = gw >> 3, h = gw & 7;
    float v = xp[(size_t)n * Dd + h * Cc + lane];
    float s = wred_sum(v * att_src[h * Cc + lane]);
    float d = wred_sum(v * att_dst[h * Cc + lane]);
    if (lane == 0) { asrc[gw] = s; adst[gw] = d; }
}

// FUSED: block per node — softmax (warp=head) + gather-aggregate + bias + residual + LN1
__global__ void __launch_bounds__(256) attagg_ln1_kernel(
        const int* __restrict__ offs, const int* __restrict__ csrc,
        const float* __restrict__ asrc, const float* __restrict__ adst,
        const float* __restrict__ aedge, float* __restrict__ wscratch,
        const float* __restrict__ xp, const float* __restrict__ m,
        const float* __restrict__ bias,
        const float* __restrict__ gamma, const float* __restrict__ beta,
        float* __restrict__ out, f16* __restrict__ ohi, f16* __restrict__ olo) {
    int n = blockIdx.x;
    int t = threadIdx.x;
    int h = t >> 5, lane = t & 31;
    __shared__ int ssrc[32];
    __shared__ float wbuf[Hh * 33];
    __shared__ float sh[40];
    __shared__ int soff, sdeg;
    if (t == 0) { soff = offs[n]; sdeg = offs[n + 1] - offs[n]; }
    __syncthreads();
    int off = soff, deg = sdeg;           // same for ALL warps in block (one node)
    const float* aeP = aedge + (size_t)h * EPN;
    int gw = n * Hh + h;
    float adstn = adst[gw];
    float al_self = lrelu(asrc[gw] + adstn + aeP[Ee + n]);
    int xcol = h * Cc + lane;
    float acc;

    if (deg <= 32) {
        int s = 0;
        float al = -3.4e38f;
        if (lane < deg) {
            s = csrc[off + lane];
            al = lrelu(asrc[s * Hh + h] + adstn + aeP[off + lane]);
        }
        float M = fmaxf(al_self, wred_max(al));
        float ex = (lane < deg) ? expf(al - M) : 0.f;
        float exs = expf(al_self - M);
        float denom = exs + wred_sum(ex);
        wbuf[h * 33 + lane] = ex / denom;
        if (h == 0 && lane < deg) ssrc[lane] = s;
        float wself = exs / denom;
        __syncthreads();
        acc = wself * xp[(size_t)n * Dd + xcol];
        for (int i = 0; i < deg; ++i)
            acc += wbuf[h * 33 + i] * xp[(size_t)ssrc[i] * Dd + xcol];
    } else {
        float* wP = wscratch + (size_t)h * Ee;
        float M = al_self;
        for (int i = lane; i < deg; i += 32) {
            int s = csrc[off + i];
            float al = lrelu(asrc[s * Hh + h] + adstn + aeP[off + i]);
            wP[off + i] = al;
            M = fmaxf(M, al);
        }
        M = wred_max(M);
        float sum = 0.f;
        for (int i = lane; i < deg; i += 32) {
            float ex = expf(wP[off + i] - M);
            wP[off + i] = ex;
            sum += ex;
        }
        float exs = expf(al_self - M);
        float denom = exs + wred_sum(sum);
        float inv = 1.f / denom;
        acc = (exs * inv) * xp[(size_t)n * Dd + xcol];
        for (int c0 = 0; c0 < deg; c0 += 32) {
            int cn = min(32, deg - c0);
            __syncthreads();
            if (h == 0 && lane < cn) ssrc[lane] = csrc[off + c0 + lane];
            if (lane < cn) wbuf[h * 33 + lane] = wP[off + c0 + lane] * inv;
            __syncthreads();
            for (int i = 0; i < cn; ++i)
                acc += wbuf[h * 33 + i] * xp[(size_t)ssrc[i] * Dd + xcol];
        }
    }

    // LayerNorm of (acc + bias + m)
    float r = acc + bias[t] + m[(size_t)n * Dd + t];
    float s = wred_sum(r);
    __syncthreads();
    if (lane == 0) sh[h] = s;
    __syncthreads();
    if (t < 8) {
        float v = sh[t];
        #pragma unroll
        for (int o = 4; o; o >>= 1) v += __shfl_xor_sync(0xffu, v, o);
        if (t == 0) sh[32] = v;
    }
    __syncthreads();
    float mean = sh[32] * (1.0f / Dd);
    float dv = r - mean;
    float sq = wred_sum(dv * dv);
    if (lane == 0) sh[h] = sq;
    __syncthreads();
    if (t < 8) {
        float v = sh[t];
        #pragma unroll
        for (int o = 4; o; o >>= 1) v += __shfl_xor_sync(0xffu, v, o);
        if (t == 0) sh[33] = v;
    }
    __syncthreads();
    float var = sh[33] * (1.0f / Dd);
    size_t oidx = (size_t)n * Dd + t;
    float val = dv * rsqrtf(var + 1e-5f) * gamma[t] + beta[t];
    out[oidx] = val;
    f16 hh, ll; split2h(val, hh, ll);
    ohi[oidx] = hh; olo[oidx] = ll;
}

// LayerNorm over D=256 of (a + b); optional fp16 split out
__global__ void ln_kernel(const float* __restrict__ a, const float* __restrict__ b,
                          const float* __restrict__ gamma, const float* __restrict__ beta,
                          float* __restrict__ out, f16* __restrict__ ohi, f16* __restrict__ olo) {
    int n = blockIdx.x;
    int t = threadIdx.x;
    int h = t >> 5, lane = t & 31;
    size_t off = (size_t)n * Dd + t;
    float r = a[off] + b[off];
    __shared__ float sh[40];
    float s = wred_sum(r);
    if (lane == 0) sh[h] = s;
    __syncthreads();
    if (t < 8) {
        float v = sh[t];
        #pragma unroll
        for (int o = 4; o; o >>= 1) v += __shfl_xor_sync(0xffu, v, o);
        if (t == 0) sh[32] = v;
    }
    __syncthreads();
    float mean = sh[32] * (1.0f / Dd);
    float dv = r - mean;
    float sq = wred_sum(dv * dv);
    if (lane == 0) sh[h] = sq;
    __syncthreads();
    if (t < 8) {
        float v = sh[t];
        #pragma unroll
        for (int o = 4; o; o >>= 1) v += __shfl_xor_sync(0xffu, v, o);
        if (t == 0) sh[33] = v;
    }
    __syncthreads();
    float var = sh[33] * (1.0f / Dd);
    float val = dv * rsqrtf(var + 1e-5f) * gamma[t] + beta[t];
    out[off] = val;
    if (ohi) {
        f16 hh, ll; split2h(val, hh, ll);
        ohi[off] = hh; olo[off] = ll;
    }
}

// ---------------- tensor-core GEMM (fp16 2-term: (Ah+Al)@Bh, cp.async pipelined) ----
__device__ __forceinline__ void mma_f16(float& d0, float& d1, float& d2, float& d3,
                                        unsigned a0, unsigned a1, unsigned a2, unsigned a3,
                                        unsigned b0, unsigned b1) {
    asm volatile("mma.sync.aligned.m16n8k16.row.col.f32.f16.f16.f32 "
                 "{%0,%1,%2,%3}, {%4,%5,%6,%7}, {%8,%9}, {%0,%1,%2,%3};\n"
                 : "+f"(d0), "+f"(d1), "+f"(d2), "+f"(d3)
                 : "r"(a0), "r"(a1), "r"(a2), "r"(a3), "r"(b0), "r"(b1));
}
__device__ __forceinline__ void cp16(unsigned dst, const void* src, int bytes) {
    asm volatile("cp.async.cg.shared.global [%0], [%1], 16, %2;\n"
                 :: "r"(dst), "l"(src), "r"(bytes));
}
__device__ __forceinline__ void cp_commit() { asm volatile("cp.async.commit_group;\n"); }
__device__ __forceinline__ void cp_wait1()  { asm volatile("cp.async.wait_group 1;\n"); }

#define GBM 128
#define GBN 128
#define GBK 32
#define GKP 40
#define GTILE (GBM*GKP)
#define GSMEM (2*3*GTILE*2)   // 61440 bytes

// C[M,N] = A[M,K] @ B[K,N]; A fp16 hi/lo [M][K], B fp16 [N][K].
template<bool BIAS, bool RELU, bool SPLIT_OUT>
__global__ void __launch_bounds__(256) gemm_f16(int M, int N, int K,
        const f16* __restrict__ Ahi, const f16* __restrict__ Alo,
        const f16* __restrict__ Bh16,
        const float* __restrict__ bias, float* __restrict__ C,
        f16* __restrict__ Chi, f16* __restrict__ Clo) {
    extern __shared__ __align__(16) f16 sdyn[];
    int tid = threadIdx.x;
    int bm0 = blockIdx.y * GBM, bn0 = blockIdx.x * GBN;
    int w = tid >> 5, lane = tid & 31;
    int wm = w & 1, wn = w >> 1;
    int g = lane >> 2, tig = lane & 3;

    int lr = tid >> 1;
    int lk = (tid & 1) * 16;

    float acc[4][4][4];
    #pragma unroll
    for (int i = 0; i < 4; ++i)
        #pragma unroll
        for (int j = 0; j < 4; ++j)
            #pragma unroll
            for (int q = 0; q < 4; ++q) acc[i][j][q] = 0.f;

    int arow = bm0 + lr;
    int abytes = (arow < M) ? 16 : 0;
    size_t aoffbase = (size_t)min(arow, M - 1) * K + lk;
    size_t boffbase = (size_t)(bn0 + lr) * K + lk;
    unsigned sA0 = (unsigned)__cvta_generic_to_shared(sdyn) + (unsigned)((lr * GKP + lk) * 2);

    auto load_stage = [&](int s, int k0) {
        unsigned base = sA0 + (unsigned)(s * 3 * GTILE * 2);
        const f16* pa = Ahi + aoffbase + k0;
        cp16(base, pa, abytes);               cp16(base + 16, pa + 8, abytes);
        const f16* pal = Alo + aoffbase + k0;
        unsigned d1 = base + GTILE * 2;
        cp16(d1, pal, abytes);                cp16(d1 + 16, pal + 8, abytes);
        const f16* pb = Bh16 + boffbase + k0;
        unsigned d2 = base + 2 * GTILE * 2;
        cp16(d2, pb, 16);                     cp16(d2 + 16, pb + 8, 16);
    };

    load_stage(0, 0);
    cp_commit();

    int s = 0;
    for (int k0 = 0; k0 < K; k0 += GBK, s ^= 1) {
        if (k0 + GBK < K) load_stage(s ^ 1, k0 + GBK);
        cp_commit();
        cp_wait1();
        __syncthreads();

        f16* Ah = sdyn + (s * 3 + 0) * GTILE;
        f16* Al = sdyn + (s * 3 + 1) * GTILE;
        f16* Bh = sdyn + (s * 3 + 2) * GTILE;

        #pragma unroll
        for (int kk = 0; kk < GBK; kk += 16) {
            unsigned afh[4][4], afl[4][4], bfh[4][2];
            int base = kk + 2 * tig;
            #pragma unroll
            for (int mt = 0; mt < 4; ++mt) {
                int r0 = wm * 64 + mt * 16 + g;
                afh[mt][0] = *reinterpret_cast<unsigned*>(&Ah[r0 * GKP + base]);
                afh[mt][1] = *reinterpret_cast<unsigned*>(&Ah[(r0 + 8) * GKP + base]);
                afh[mt][2] = *reinterpret_cast<unsigned*>(&Ah[r0 * GKP + base + 8]);
                afh[mt][3] = *reinterpret_cast<unsigned*>(&Ah[(r0 + 8) * GKP + base + 8]);
                afl[mt][0] = *reinterpret_cast<unsigned*>(&Al[r0 * GKP + base]);
                afl[mt][1] = *reinterpret_cast<unsigned*>(&Al[(r0 + 8) * GKP + base]);
                afl[mt][2] = *reinterpret_cast<unsigned*>(&Al[r0 * GKP + base + 8]);
                afl[mt][3] = *reinterpret_cast<unsigned*>(&Al[(r0 + 8) * GKP + base + 8]);
            }
            #pragma unroll
            for (int nt = 0; nt < 4; ++nt) {
                int c0 = wn * 32 + nt * 8 + g;
                bfh[nt][0] = *reinterpret_cast<unsigned*>(&Bh[c0 * GKP + base]);
                bfh[nt][1] = *reinterpret_cast<unsigned*>(&Bh[c0 * GKP + base + 8]);
            }
            #pragma unroll
            for (int mt = 0; mt < 4; ++mt)
                #pragma unroll
                for (int nt = 0; nt < 4; ++nt) {
                    mma_f16(acc[mt][nt][0], acc[mt][nt][1], acc[mt][nt][2], acc[mt][nt][3],
                            afh[mt][0], afh[mt][1], afh[mt][2], afh[mt][3],
                            bfh[nt][0], bfh[nt][1]);
                    mma_f16(acc[mt][nt][0], acc[mt][nt][1], acc[mt][nt][2], acc[mt][nt][3],
                            afl[mt][0], afl[mt][1], afl[mt][2], afl[mt][3],
                            bfh[nt][0], bfh[nt][1]);
                }
        }
        __syncthreads();
    }

    #pragma unroll
    for (int mt = 0; mt < 4; ++mt) {
        #pragma unroll
        for (int half = 0; half < 2; ++half) {
            int row = bm0 + wm * 64 + mt * 16 + g + half * 8;
            if (row < M) {
                #pragma unroll
                for (int nt = 0; nt < 4; ++nt) {
                    int col = bn0 + wn * 32 + nt * 8 + 2 * tig;
                    float vx = acc[mt][nt][half * 2 + 0];
                    float vy = acc[mt][nt][half * 2 + 1];
                    if (BIAS) { vx += bias[col]; vy += bias[col + 1]; }
                    if (RELU) { vx = fmaxf(vx, 0.f); vy = fmaxf(vy, 0.f); }
                    if (SPLIT_OUT) {
                        f16 hx, lx, hy, ly;
                        split2h(vx, hx, lx); split2h(vy, hy, ly);
                        *reinterpret_cast<__half2*>(Chi + (size_t)row * N + col) =
                            __halves2half2(hx, hy);
                        *reinterpret_cast<__half2*>(Clo + (size_t)row * N + col) =
                            __halves2half2(lx, ly);
                    } else {
                        float2 v; v.x = vx; v.y = vy;
                        *reinterpret_cast<float2*>(C + (size_t)row * N + col) = v;
                    }
                }
            }
        }
    }
}

// ---------------- orchestration ----------------
static inline void* symaddr(const void* sym) {
    void* p = nullptr;
    cudaGetSymbolAddress(&p, sym);
    return p;
}

extern "C" void kernel_launch(void* const* d_in, const int* in_sizes, int n_in,
                              void* d_out, int out_size) {
    const float* x        = (const float*)d_in[0];
    const void*  ei       = d_in[1];
    const float* edge_attr= (const float*)d_in[2];
    const float* W        = (const float*)d_in[3];
    const float* att_src  = (const float*)d_in[4];
    const float* att_dst  = (const float*)d_in[5];
    const float* att_edge = (const float*)d_in[6];
    const float* W_edge   = (const float*)d_in[7];
    const float* bias     = (const float*)d_in[8];
    const float* ffn_w1   = (const float*)d_in[9];
    const float* ffn_b1   = (const float*)d_in[10];
    const float* ffn_w2   = (const float*)d_in[11];
    const float* ffn_b2   = (const float*)d_in[12];
    const float* ln1_g    = (const float*)d_in[13];
    const float* ln1_b    = (const float*)d_in[14];
    const float* ln2_g    = (const float*)d_in[15];
    const float* ln2_b    = (const float*)d_in[16];
    float* out = (float*)d_out;

    float* pm     = (float*)symaddr(g_m);
    f16*   pmhi   = (f16*)symaddr(g_mhi);
    f16*   pmlo   = (f16*)symaddr(g_mlo);
    float* pxp    = (float*)symaddr(g_xp);
    float* pm1    = (float*)symaddr(g_m1);
    f16*   pm1hi  = (f16*)symaddr(g_m1hi);
    f16*   pm1lo  = (f16*)symaddr(g_m1lo);
    f16*   phhi   = (f16*)symaddr(g_hhi);
    f16*   phlo   = (f16*)symaddr(g_hlo);
    float* ph2    = (float*)symaddr(g_h2);
    float* pw     = (float*)symaddr(g_w);
    float* paedge = (float*)symaddr(g_aedge);
    float* pasrc  = (float*)symaddr(g_asrc);
    float* padst  = (float*)symaddr(g_adst);
    float* peasum = (float*)symaddr(g_easum);
    float* peamean= (float*)symaddr(g_eamean);
    float* pv     = (float*)symaddr(g_v);
    int*   psrc   = (int*)symaddr(g_src32);
    int*   pdst   = (int*)symaddr(g_dst32);
    int*   pdegi  = (int*)symaddr(g_degi);
    int*   poffs  = (int*)symaddr(g_offs);
    int*   pcur   = (int*)symaddr(g_cursor);
    int*   pcsrc  = (int*)symaddr(g_csrc);
    int*   pposof = (int*)symaddr(g_posof);
    int*   pbsum  = (int*)symaddr(g_bsum);
    int*   pboff  = (int*)symaddr(g_boff);
    f16*   pWh    = (f16*)symaddr(g_Wh);
    f16*   pw1h   = (f16*)symaddr(g_w1h);
    f16*   pw2h   = (f16*)symaddr(g_w2h);

    const int T = 256;
    auto blk = [](long long n, int t) { return (unsigned)((n + t - 1) / t); };

    cudaFuncSetAttribute(gemm_f16<false,false,false>,
                         cudaFuncAttributeMaxDynamicSharedMemorySize, GSMEM);
    cudaFuncSetAttribute(gemm_f16<true,true,true>,
                         cudaFuncAttributeMaxDynamicSharedMemorySize, GSMEM);
    cudaFuncSetAttribute(gemm_f16<true,false,false>,
                         cudaFuncAttributeMaxDynamicSharedMemorySize, GSMEM);

    dim3 gProj(Dd / 128, (Nn + 127) / 128);
    dim3 gF1(D4 / 128, (Nn + 127) / 128);
    dim3 gF2(Dd / 128, (Nn + 127) / 128);
    unsigned gW = blk((long long)Nn * Hh * 32, T);

    // ---- precompute, ordered so launch #4 is the proj GEMM (ncu target) ----
    cvtT_kernel<<<blk((long long)Dd * Dd, T), T>>>(W, Dd, Dd, pWh);                  // 1
    split_act_kernel<<<blk((long long)Nn * Dd, T), T>>>(x, pm, pmhi, pmlo, Nn * Dd); // 2
    zeroi_kernel<<<blk(Nn, T), T>>>(pdegi, Nn);                                      // 3
    gemm_f16<false, false, false><<<gProj, 256, GSMEM>>>(                            // 4 (layer 0 proj)
        Nn, Dd, Dd, pmhi, pmlo, pWh, nullptr, pxp, nullptr, nullptr);
    zerof_kernel<<<blk((long long)Nn * EDd, T), T>>>(peasum, Nn * EDd);              // 5
    convert_idx_kernel<<<blk(Ee, T), T>>>(ei, psrc, pdst, pdegi);                    // 6
    scan1_kernel<<<SCNB, SCB>>>(pdegi, poffs, pbsum);
    scan2_kernel<<<1, SCB>>>(pbsum, pboff);
    scan3_kernel<<<SCNB, SCB>>>(poffs, pcur, pboff);
    scatter_kernel<<<blk(Ee, T), T>>>(psrc, pdst, pcur, pcsrc, pposof);
    easum_kernel<<<blk((long long)Ee * EDd, T), T>>>(pdst, edge_attr, peasum);
    eamean_kernel<<<blk((long long)Nn * EDd, T), T>>>(peasum, pdegi, peamean);
    v_kernel<<<1, 128>>>(W_edge, att_edge, pv);
    aedge_kernel<<<blk((long long)EPN, T), T>>>(edge_attr, peamean, pv, pposof, paedge);
    for (int i = 0; i < Ll; ++i) {
        cvtT_kernel<<<blk((long long)Dd * D4, T), T>>>(
            ffn_w1 + (size_t)i * Dd * D4, Dd, D4, pw1h + (size_t)i * Dd * D4);
        cvtT_kernel<<<blk((long long)D4 * Dd, T), T>>>(
            ffn_w2 + (size_t)i * D4 * Dd, D4, Dd, pw2h + (size_t)i * D4 * Dd);
    }

    for (int i = 0; i < Ll; ++i) {
        if (i > 0) {
            gemm_f16<false, false, false><<<gProj, 256, GSMEM>>>(
                Nn, Dd, Dd, pmhi, pmlo, pWh, nullptr, pxp, nullptr, nullptr);
        }
        asrc_adst_kernel<<<gW, T>>>(pxp, att_src, att_dst, pasrc, padst);
        attagg_ln1_kernel<<<Nn, 256>>>(poffs, pcsrc, pasrc, padst, paedge, pw,
                                       pxp, pm, bias,
                                       ln1_g + i * Dd, ln1_b + i * Dd, pm1, pm1hi, pm1lo);
        gemm_f16<true, true, true><<<gF1, 256, GSMEM>>>(
            Nn, D4, Dd, pm1hi, pm1lo, pw1h + (size_t)i * Dd * D4,
            ffn_b1 + (size_t)i * D4, nullptr, phhi, phlo);
        gemm_f16<true, false, false><<<gF2, 256, GSMEM>>>(
            Nn, Dd, D4, phhi, phlo, pw2h + (size_t)i * D4 * Dd,
            ffn_b2 + (size_t)i * Dd, ph2, nullptr, nullptr);
        if (i == Ll - 1) {
            ln_kernel<<<Nn, 256>>>(ph2, pm1, ln2_g + i * Dd, ln2_b + i * Dd,
                                   out, nullptr, nullptr);
        } else {
            ln_kernel<<<Nn, 256>>>(ph2, pm1, ln2_g + i * Dd, ln2_b + i * Dd,
                                   pm, pmhi, pmlo);
        }
    }
}